// round 1
// baseline (speedup 1.0000x reference)
#include <cuda_runtime.h>

#define B_    512
#define BAG_  32
#define H_    1024
#define C_    53
#define N_    (B_*BAG_)   // 16384
#define EPS_  1e-8f

// ---------------- device scratch (no allocations allowed) ----------------
__device__ float g_bag[B_*H_];   // bag_reps  (512 x 1024)
__device__ float g_nb [B_];      // ||bag_reps||
__device__ float g_nr [N_];      // ||rep[b,j]||
__device__ float g_pos[N_];      // exp(pos_sim / T)
__device__ float g_neg[N_];      // sum_{b!=c} exp(pair/T)

__device__ __forceinline__ float warp_sum(float v) {
    #pragma unroll
    for (int o = 16; o; o >>= 1) v += __shfl_down_sync(0xffffffffu, v, o);
    return v;  // valid in lane 0
}
__device__ __forceinline__ float warp_max(float v) {
    #pragma unroll
    for (int o = 16; o; o >>= 1) v = fmaxf(v, __shfl_xor_sync(0xffffffffu, v, o));
    return v;  // valid in all lanes
}

// ---------------- K0: zero the neg accumulator ----------------
__global__ void k_zero() {
    int i = blockIdx.x * blockDim.x + threadIdx.x;
    if (i < N_) g_neg[i] = 0.0f;
}

// ---------------- K1: per-batch attention pooling + norms + pos ----------------
// grid = 512 blocks, 256 threads
__global__ void __launch_bounds__(256) k_bag(
    const float* __restrict__ rep, const float* __restrict__ aug,
    const float* __restrict__ rel_table, const int* __restrict__ labels,
    const float* __restrict__ tptr)
{
    int b = blockIdx.x;
    int tid = threadIdx.x, wid = tid >> 5, lane = tid & 31;
    const float* repb = rep + (size_t)b * BAG_ * H_;
    const float* augb = aug + (size_t)b * BAG_ * H_;
    const float* rel  = rel_table + (size_t)labels[b] * H_;
    float invT = 1.0f / tptr[0];

    __shared__ float s_scores[BAG_];
    __shared__ float s_alpha[BAG_];
    __shared__ float s_red[8];

    // each warp handles 4 sentences: dot with rel, self-norms, rep.aug
    for (int j = wid; j < BAG_; j += 8) {
        const float* r = repb + j * H_;
        const float* a = augb + j * H_;
        float ds = 0.f, dr = 0.f, da = 0.f, dra = 0.f;
        for (int h = lane; h < H_; h += 32) {
            float rv = r[h], av = a[h];
            ds  = fmaf(rel[h], rv, ds);
            dr  = fmaf(rv, rv, dr);
            da  = fmaf(av, av, da);
            dra = fmaf(rv, av, dra);
        }
        ds = warp_sum(ds); dr = warp_sum(dr); da = warp_sum(da); dra = warp_sum(dra);
        if (lane == 0) {
            s_scores[j] = ds * (1.0f / 32.0f);      // / sqrt(H)
            float nr = sqrtf(dr), na = sqrtf(da);
            g_nr[b * BAG_ + j] = nr;
            float psim = dra / fmaxf(nr * na, EPS_);
            g_pos[b * BAG_ + j] = expf(psim * invT);
        }
    }
    __syncthreads();

    // softmax over 32 scores (warp 0)
    if (tid < 32) {
        float v = s_scores[tid];
        float m = warp_max(v);
        float e = expf(v - m);
        float s = warp_sum(e);
        s = __shfl_sync(0xffffffffu, s, 0);
        s_alpha[tid] = e / s;
    }
    __syncthreads();

    // bag_reps[h] = sum_j alpha_j * rep[b,j,h]; accumulate ||bag||^2
    float nb_part = 0.f;
    for (int h = tid; h < H_; h += 256) {
        float acc = 0.f;
        #pragma unroll
        for (int j = 0; j < BAG_; ++j)
            acc = fmaf(s_alpha[j], repb[j * H_ + h], acc);
        g_bag[b * H_ + h] = acc;
        nb_part = fmaf(acc, acc, nb_part);
    }
    nb_part = warp_sum(nb_part);
    if (lane == 0) s_red[wid] = nb_part;
    __syncthreads();
    if (tid == 0) {
        float s = 0.f;
        #pragma unroll
        for (int w = 0; w < 8; ++w) s += s_red[w];
        g_nb[b] = sqrtf(s);
    }
}

// ---------------- K2: bag_out = bag_reps @ cls_w.T + cls_b ----------------
// grid = 512 blocks, 256 threads
__global__ void __launch_bounds__(256) k_clsout(
    const float* __restrict__ cls_w, const float* __restrict__ cls_b,
    float* __restrict__ out)
{
    int b = blockIdx.x;
    int tid = threadIdx.x, wid = tid >> 5, lane = tid & 31;
    __shared__ float sb[H_];
    for (int h = tid; h < H_; h += 256) sb[h] = g_bag[b * H_ + h];
    __syncthreads();
    for (int c = wid; c < C_; c += 8) {
        const float* w = cls_w + (size_t)c * H_;
        float acc = 0.f;
        for (int h = lane; h < H_; h += 32) acc = fmaf(sb[h], w[h], acc);
        acc = warp_sum(acc);
        if (lane == 0) out[b * C_ + c] = acc + cls_b[c];
    }
}

// ---------------- K3: pair GEMM (bag @ rep^T) + fused exp/reduce epilogue ----
// A = g_bag (512 x 1024), B = rep viewed as (16384 x 1024), both K-contiguous.
// Block tile 64(c) x 64(bj), BK=16, 256 threads, 4x4 per thread.
#define BM 64
#define BN 64
#define BK 16

__global__ void __launch_bounds__(256) k_pair(
    const float* __restrict__ rep, const float* __restrict__ tptr)
{
    __shared__ float As[BK][BM + 4];
    __shared__ float Bs[BK][BN + 4];
    int tid = threadIdx.x;
    int m0 = blockIdx.y * BM;   // c tile
    int n0 = blockIdx.x * BN;   // (b,j) tile, n = b*32 + j
    float invT = 1.0f / tptr[0];

    int lm = tid >> 2;          // 0..63 : row within tile
    int lk = (tid & 3) * 4;     // 0,4,8,12 : k offset (float4)
    const float* Ag = g_bag + (size_t)(m0 + lm) * H_ + lk;
    const float* Bg = rep   + (size_t)(n0 + lm) * H_ + lk;

    int ty = tid >> 4, tx = tid & 15;
    float acc[4][4] = {};

    for (int k0 = 0; k0 < H_; k0 += BK) {
        float4 av = *(const float4*)(Ag + k0);
        float4 bv = *(const float4*)(Bg + k0);
        As[lk + 0][lm] = av.x; As[lk + 1][lm] = av.y;
        As[lk + 2][lm] = av.z; As[lk + 3][lm] = av.w;
        Bs[lk + 0][lm] = bv.x; Bs[lk + 1][lm] = bv.y;
        Bs[lk + 2][lm] = bv.z; Bs[lk + 3][lm] = bv.w;
        __syncthreads();
        #pragma unroll
        for (int kk = 0; kk < BK; ++kk) {
            float4 a  = *(const float4*)&As[kk][ty * 4];
            float4 bb = *(const float4*)&Bs[kk][tx * 4];
            acc[0][0] = fmaf(a.x, bb.x, acc[0][0]);
            acc[0][1] = fmaf(a.x, bb.y, acc[0][1]);
            acc[0][2] = fmaf(a.x, bb.z, acc[0][2]);
            acc[0][3] = fmaf(a.x, bb.w, acc[0][3]);
            acc[1][0] = fmaf(a.y, bb.x, acc[1][0]);
            acc[1][1] = fmaf(a.y, bb.y, acc[1][1]);
            acc[1][2] = fmaf(a.y, bb.z, acc[1][2]);
            acc[1][3] = fmaf(a.y, bb.w, acc[1][3]);
            acc[2][0] = fmaf(a.z, bb.x, acc[2][0]);
            acc[2][1] = fmaf(a.z, bb.y, acc[2][1]);
            acc[2][2] = fmaf(a.z, bb.z, acc[2][2]);
            acc[2][3] = fmaf(a.z, bb.w, acc[2][3]);
            acc[3][0] = fmaf(a.w, bb.x, acc[3][0]);
            acc[3][1] = fmaf(a.w, bb.y, acc[3][1]);
            acc[3][2] = fmaf(a.w, bb.z, acc[3][2]);
            acc[3][3] = fmaf(a.w, bb.w, acc[3][3]);
        }
        __syncthreads();
    }

    // epilogue: pair = dot / max(nb[c]*nr[n], eps); neg[c,j] += exp(pair/T) for b != c
    float nbv[4];
    #pragma unroll
    for (int i = 0; i < 4; ++i) nbv[i] = g_nb[m0 + ty * 4 + i];
    #pragma unroll
    for (int j = 0; j < 4; ++j) {
        int n  = n0 + tx * 4 + j;
        int bb = n >> 5;          // sample index b
        int jj = n & 31;          // sentence index j
        float nrv = g_nr[n];
        #pragma unroll
        for (int i = 0; i < 4; ++i) {
            int c = m0 + ty * 4 + i;
            float pair = acc[i][j] / fmaxf(nbv[i] * nrv, EPS_);
            if (bb != c)
                atomicAdd(&g_neg[c * BAG_ + jj], expf(pair * invT));
        }
    }
}

// ---------------- K4: final loss = mean log1p(neg/pos) ----------------
__global__ void __launch_bounds__(256) k_loss(float* __restrict__ out, int loss_idx) {
    int tid = threadIdx.x;
    __shared__ float s_red[8];
    float s = 0.f;
    for (int i = tid; i < N_; i += 256)
        s += log1pf(g_neg[i] / g_pos[i]);   // == -log(pos/(pos+neg))
    s = warp_sum(s);
    if ((tid & 31) == 0) s_red[tid >> 5] = s;
    __syncthreads();
    if (tid == 0) {
        float t = 0.f;
        #pragma unroll
        for (int w = 0; w < 8; ++w) t += s_red[w];
        out[loss_idx] = t / (float)N_;
    }
}

// ---------------- launch ----------------
extern "C" void kernel_launch(void* const* d_in, const int* in_sizes, int n_in,
                              void* d_out, int out_size) {
    const float* rep    = (const float*)d_in[0];  // sent_reps (512,32,1024)
    const float* aug    = (const float*)d_in[1];  // aug_sent_reps
    const float* rel    = (const float*)d_in[2];  // rel_table (53,1024)
    const float* cls_w  = (const float*)d_in[3];  // (53,1024)
    const float* cls_b  = (const float*)d_in[4];  // (53,)
    const int*   labels = (const int*)d_in[5];    // (512,)
    const float* temp   = (const float*)d_in[6];  // scalar
    float* out = (float*)d_out;                   // [512*53 bag_out][1 loss]

    k_zero<<<(N_ + 255) / 256, 256>>>();
    k_bag<<<B_, 256>>>(rep, aug, rel, labels, temp);
    k_clsout<<<B_, 256>>>(cls_w, cls_b, out);
    dim3 g3(N_ / BN, B_ / BM);   // (256, 8)
    k_pair<<<g3, 256>>>(rep, temp);
    k_loss<<<1, 256>>>(out, out_size - 1);
}

// round 3
// speedup vs baseline: 3.8966x; 3.8966x over previous
#include <cuda_runtime.h>
#include <cuda_bf16.h>

#define B_    512
#define BAG_  32
#define H_    1024
#define C_    53
#define N_    (B_*BAG_)   // 16384
#define EPS_  1e-8f

// ---------------- device scratch ----------------
// chunked+pre-swizzled bf16 layouts for the pair GEMM:
// elem(n, k) lives at chunk kc=k>>6, byte = kc*ROWS*128 + (n>>3)*1024 + sw((n&7)*128 + (k&63)*2)
__device__ __align__(128) __nv_bfloat16 g_rep_bf[N_*H_];
__device__ __align__(128) __nv_bfloat16 g_bag_bf[B_*H_];
__device__ float g_bag[B_*H_];   // bag_reps fp32 (classifier)
__device__ float g_rnb[B_];      // 1/||bag||
__device__ float g_rnr[N_];      // 1/||rep||
__device__ float g_pos[N_];      // exp(pos_sim/T)
__device__ float g_neg[N_];      // sum_{b!=c} exp(pair/T)

__device__ __forceinline__ float warp_sum(float v) {
    #pragma unroll
    for (int o = 16; o; o >>= 1) v += __shfl_down_sync(0xffffffffu, v, o);
    return v;
}
__device__ __forceinline__ float warp_max(float v) {
    #pragma unroll
    for (int o = 16; o; o >>= 1) v = fmaxf(v, __shfl_xor_sync(0xffffffffu, v, o));
    return v;
}

// ---------------- PTX helpers (all baseline sm_90-or-older; no 'a' features) ----
#define MBAR_INIT(addr, cnt) \
    asm volatile("mbarrier.init.shared.b64 [%0], %1;" :: "r"(addr), "r"(cnt) : "memory")

#define MBAR_WAIT(addr, par) do {                                              \
    unsigned _m = (addr), _p = (par), _d;                                      \
    asm volatile("{\n\t.reg .pred p;\n\t"                                      \
        "mbarrier.try_wait.parity.acquire.cta.shared::cta.b64 p, [%1], %2;\n\t"\
        "selp.b32 %0,1,0,p;\n\t}" : "=r"(_d) : "r"(_m), "r"(_p) : "memory");   \
    if (!_d) {                                                                 \
        asm volatile("{\n\t.reg .pred P1;\n\t"                                 \
        "WL_%=:\n\t"                                                           \
        "mbarrier.try_wait.parity.acquire.cta.shared::cta.b64 P1, [%0], %1, 0x989680;\n\t" \
        "@P1 bra.uni WD_%=;\n\t"                                               \
        "bra.uni WL_%=;\n\t"                                                   \
        "WD_%=:\n\t}" :: "r"(_m), "r"(_p) : "memory");                         \
    }                                                                          \
} while (0)

#define LDSM4(r, addr) \
    asm volatile("ldmatrix.sync.aligned.m8n8.x4.shared.b16 {%0,%1,%2,%3}, [%4];" \
        : "=r"((r)[0]), "=r"((r)[1]), "=r"((r)[2]), "=r"((r)[3]) : "r"(addr))

#define MMA_BF16(c, a, b0v, b1v) \
    asm volatile("mma.sync.aligned.m16n8k16.row.col.f32.bf16.bf16.f32 " \
        "{%0,%1,%2,%3}, {%4,%5,%6,%7}, {%8,%9}, {%0,%1,%2,%3};" \
        : "+f"((c)[0]), "+f"((c)[1]), "+f"((c)[2]), "+f"((c)[3]) \
        : "r"((a)[0]), "r"((a)[1]), "r"((a)[2]), "r"((a)[3]), "r"(b0v), "r"(b1v))

__device__ __forceinline__ void bulk_cp(unsigned dst, const void* src,
                                        unsigned bytes, unsigned mbar) {
    asm volatile(
        "cp.async.bulk.shared::cta.global.mbarrier::complete_tx::bytes [%0], [%1], %2, [%3];"
        :: "r"(dst), "l"(src), "r"(bytes), "r"(mbar) : "memory");
}
__device__ __forceinline__ void mbar_expect(unsigned mbar, unsigned bytes) {
    asm volatile("mbarrier.arrive.expect_tx.shared.b64 _, [%0], %1;"
                 :: "r"(mbar), "r"(bytes) : "memory");
}

// swizzled byte offset inside a 1KB 8-row group (row3 = row&7, kb = byte col 0..127)
__device__ __forceinline__ unsigned sw128(unsigned byo) {
    return byo ^ ((byo >> 3) & 0x70);
}

// ---------------- K0: zero neg ----------------
__global__ void k_zero() {
    int i = blockIdx.x * blockDim.x + threadIdx.x;
    if (i < N_) g_neg[i] = 0.0f;
}

// ---------------- K1: attention pooling + norms + pos + chunked bf16 writes ----
__global__ void __launch_bounds__(256) k_bag(
    const float* __restrict__ rep, const float* __restrict__ aug,
    const float* __restrict__ rel_table, const int* __restrict__ labels,
    const float* __restrict__ tptr)
{
    int b = blockIdx.x;
    int tid = threadIdx.x, wid = tid >> 5, lane = tid & 31;
    const float* repb = rep + (size_t)b * BAG_ * H_;
    const float* augb = aug + (size_t)b * BAG_ * H_;
    const float2* rel2 = (const float2*)(rel_table + (size_t)labels[b] * H_);
    float invT = 1.0f / tptr[0];

    __shared__ float s_scores[BAG_];
    __shared__ float s_alpha[BAG_];
    __shared__ float s_red[8];

    // each warp: 4 sentences
    for (int j = wid; j < BAG_; j += 8) {
        const float2* r2 = (const float2*)(repb + (size_t)j * H_);
        const float2* a2 = (const float2*)(augb + (size_t)j * H_);
        int n = b * BAG_ + j;
        unsigned swo = sw128((unsigned)(n & 7) * 128u + (unsigned)lane * 4u);
        __nv_bfloat162* dst = (__nv_bfloat162*)g_rep_bf
                            + (size_t)(n >> 3) * 256 + (swo >> 2);
        float ds = 0.f, dr = 0.f, da = 0.f, dra = 0.f;
        #pragma unroll 4
        for (int u = 0; u < 16; ++u) {          // pair index t = lane + 32u
            int t = lane + 32 * u;
            float2 rv = r2[t], av = a2[t], rl = rel2[t];
            dst[(size_t)u * (N_ * 32 / 16) * 16] = // chunk stride = N_*32 bf162... see below
                __floats2bfloat162_rn(rv.x, rv.y);
            ds  = fmaf(rl.x, rv.x, fmaf(rl.y, rv.y, ds));
            dr  = fmaf(rv.x, rv.x, fmaf(rv.y, rv.y, dr));
            da  = fmaf(av.x, av.x, fmaf(av.y, av.y, da));
            dra = fmaf(rv.x, av.x, fmaf(rv.y, av.y, dra));
        }
        ds = warp_sum(ds); dr = warp_sum(dr); da = warp_sum(da); dra = warp_sum(dra);
        if (lane == 0) {
            s_scores[j] = ds * (1.0f / 32.0f);
            float nr = sqrtf(dr), na = sqrtf(da);
            g_rnr[n] = 1.0f / nr;
            float psim = dra / fmaxf(nr * na, EPS_);
            g_pos[n] = expf(psim * invT);
        }
    }
    __syncthreads();

    if (tid < 32) {
        float v = s_scores[tid];
        float m = warp_max(v);
        float e = expf(v - m);
        float s = warp_sum(e);
        s = __shfl_sync(0xffffffffu, s, 0);
        s_alpha[tid] = e / s;
    }
    __syncthreads();

    // bag pooling (pairs): thread handles pair indices tid and tid+256
    float nb_part = 0.f;
    const float2* rp2 = (const float2*)repb;
    #pragma unroll
    for (int q = 0; q < 2; ++q) {
        int ph = tid + q * 256;                  // pair index, h = 2*ph
        float a0 = 0.f, a1 = 0.f;
        #pragma unroll
        for (int j = 0; j < BAG_; ++j) {
            float2 v = rp2[(size_t)j * (H_ / 2) + ph];
            a0 = fmaf(s_alpha[j], v.x, a0);
            a1 = fmaf(s_alpha[j], v.y, a1);
        }
        ((float2*)g_bag)[(size_t)b * (H_ / 2) + ph] = make_float2(a0, a1);
        int kc = ph >> 5;                        // = h>>6
        unsigned swo = sw128((unsigned)(b & 7) * 128u + (unsigned)(ph & 31) * 4u);
        ((__nv_bfloat162*)g_bag_bf)[(size_t)kc * (B_ * 32) + (size_t)(b >> 3) * 256 + (swo >> 2)]
            = __floats2bfloat162_rn(a0, a1);
        nb_part = fmaf(a0, a0, fmaf(a1, a1, nb_part));
    }
    nb_part = warp_sum(nb_part);
    if (lane == 0) s_red[wid] = nb_part;
    __syncthreads();
    if (tid == 0) {
        float s = 0.f;
        #pragma unroll
        for (int w = 0; w < 8; ++w) s += s_red[w];
        g_rnb[b] = 1.0f / sqrtf(s);
    }
}

// ---------------- K2: classifier ----------------
__global__ void __launch_bounds__(256) k_clsout(
    const float* __restrict__ cls_w, const float* __restrict__ cls_b,
    float* __restrict__ out)
{
    int b = blockIdx.x;
    int tid = threadIdx.x, wid = tid >> 5, lane = tid & 31;
    __shared__ float sb[H_];
    for (int h = tid; h < H_; h += 256) sb[h] = g_bag[b * H_ + h];
    __syncthreads();
    for (int c = wid; c < C_; c += 8) {
        const float* w = cls_w + (size_t)c * H_;
        float acc = 0.f;
        for (int h = lane; h < H_; h += 32) acc = fmaf(sb[h], w[h], acc);
        acc = warp_sum(acc);
        if (lane == 0) out[b * C_ + c] = acc + cls_b[c];
    }
}

// ---------------- K3: bf16 HMMA pair GEMM, bulk-copy pipelined ----------------
// BM=128(c) x BN=128(n), BK=64 per chunk, 16 chunks, 3-stage pipeline.
#define STAGES 3
#define STAGE_BYTES 32768
#define NKC 16
#define PAIR_SMEM (STAGES * STAGE_BYTES)   // 98304

__global__ void __launch_bounds__(256, 2) k_pair_hmma(const float* __restrict__ tptr)
{
    extern __shared__ __align__(16) char smem[];
    __shared__ __align__(8) unsigned long long mbars[STAGES];
    unsigned smem_u = (unsigned)__cvta_generic_to_shared(smem);
    unsigned mbar_u = (unsigned)__cvta_generic_to_shared(mbars);
    int tid = threadIdx.x, wid = tid >> 5, lane = tid & 31;
    int wm = wid >> 2, wn = wid & 3;
    int m0 = blockIdx.y * 128, n0 = blockIdx.x * 128;

    if (tid == 0) {
        #pragma unroll
        for (int s = 0; s < STAGES; ++s) MBAR_INIT(mbar_u + 8 * s, 1);
    }
    __syncthreads();

    const char* Asrc = (const char*)g_bag_bf;
    const char* Bsrc = (const char*)g_rep_bf;
    if (tid == 0) {
        #pragma unroll
        for (int s = 0; s < STAGES; ++s) {
            unsigned mb = mbar_u + 8 * s;
            mbar_expect(mb, 2 * 16384u);
            unsigned d = smem_u + s * STAGE_BYTES;
            bulk_cp(d,          Asrc + ((size_t)s * B_ + m0) * 128, 16384u, mb);
            bulk_cp(d + 16384u, Bsrc + ((size_t)s * N_ + n0) * 128, 16384u, mb);
        }
    }

    // per-thread ldmatrix address components
    unsigned xr   = (unsigned)(lane & 7) * 16u;
    unsigned hk16 = (unsigned)(lane >> 4) * 16u;          // A: k half select
    unsigned kb16 = (unsigned)((lane >> 3) & 1) * 16u;    // B: k half select
    unsigned aoffb = (unsigned)((wm * 64 + (lane & 15)) * 128);
    unsigned boffb = (unsigned)((wn * 32 + ((lane >> 4) & 1) * 8 + (lane & 7)) * 128) + 16384u;

    float acc[4][4][4] = {};

    #pragma unroll 1
    for (int kc = 0; kc < NKC; ++kc) {
        int st = kc % 3;
        MBAR_WAIT(mbar_u + 8 * st, (kc / 3) & 1);
        unsigned base = smem_u + st * STAGE_BYTES;
        #pragma unroll
        for (int ks = 0; ks < 4; ++ks) {
            unsigned afr[4][4], bfr[2][4];
            unsigned ksa = ((unsigned)(ks * 32) + hk16) ^ xr;
            unsigned ksb = ((unsigned)(ks * 32) + kb16) ^ xr;
            #pragma unroll
            for (int mt = 0; mt < 4; ++mt)
                LDSM4(afr[mt], base + aoffb + mt * 2048u + ksa);
            #pragma unroll
            for (int np = 0; np < 2; ++np)
                LDSM4(bfr[np], base + boffb + np * 2048u + ksb);
            #pragma unroll
            for (int mt = 0; mt < 4; ++mt)
                #pragma unroll
                for (int nt = 0; nt < 4; ++nt)
                    MMA_BF16(acc[mt][nt], afr[mt],
                             bfr[nt >> 1][(nt & 1) * 2], bfr[nt >> 1][(nt & 1) * 2 + 1]);
        }
        __syncthreads();
        if (tid == 0 && kc + STAGES < NKC) {
            unsigned mb = mbar_u + 8 * st;
            mbar_expect(mb, 2 * 16384u);
            unsigned d = smem_u + st * STAGE_BYTES;
            bulk_cp(d,          Asrc + ((size_t)(kc + STAGES) * B_ + m0) * 128, 16384u, mb);
            bulk_cp(d + 16384u, Bsrc + ((size_t)(kc + STAGES) * N_ + n0) * 128, 16384u, mb);
        }
    }

    // ---- epilogue: exp + diagonal skip, 4-pass smem reduce over wn, atomics ----
    float* sbuf  = (float*)smem;                    // [128][34] floats = 17408 B
    float* s_rnr = (float*)(smem + 17408);
    float* s_rnb = (float*)(smem + 17408 + 512);
    if (tid < 128) { s_rnr[tid] = g_rnr[n0 + tid]; s_rnb[tid] = g_rnb[m0 + tid]; }
    __syncthreads();
    float invT = 1.0f / tptr[0];
    int bglob = (n0 >> 5) + wn;                     // sample index of this warp's 32 cols
    int r0base = wm * 64 + (lane >> 2);

    for (int pass = 0; pass < 4; ++pass) {
        if (wn == pass) {
            #pragma unroll
            for (int mt = 0; mt < 4; ++mt) {
                int r0 = r0base + mt * 16, r1 = r0 + 8;
                float f0 = s_rnb[r0] * invT, f1 = s_rnb[r1] * invT;
                bool sk0 = (m0 + r0) == bglob, sk1 = (m0 + r1) == bglob;
                #pragma unroll
                for (int nt = 0; nt < 4; ++nt) {
                    int jj = nt * 8 + (lane & 3) * 2;
                    float rn0 = s_rnr[wn * 32 + jj], rn1 = s_rnr[wn * 32 + jj + 1];
                    float e00 = sk0 ? 0.f : __expf(acc[mt][nt][0] * f0 * rn0);
                    float e01 = sk0 ? 0.f : __expf(acc[mt][nt][1] * f0 * rn1);
                    float e10 = sk1 ? 0.f : __expf(acc[mt][nt][2] * f1 * rn0);
                    float e11 = sk1 ? 0.f : __expf(acc[mt][nt][3] * f1 * rn1);
                    float* p0 = &sbuf[r0 * 34 + jj];
                    float* p1 = &sbuf[r1 * 34 + jj];
                    if (pass == 0) { p0[0] = e00; p0[1] = e01; p1[0] = e10; p1[1] = e11; }
                    else           { p0[0] += e00; p0[1] += e01; p1[0] += e10; p1[1] += e11; }
                }
            }
        }
        __syncthreads();
    }
    for (int e = tid; e < 4096; e += 256) {
        int lc = e >> 5, jj = e & 31;
        atomicAdd(&g_neg[(m0 + lc) * BAG_ + jj], sbuf[lc * 34 + jj]);
    }
}

// ---------------- K4: loss ----------------
__global__ void __launch_bounds__(256) k_loss(float* __restrict__ out, int loss_idx) {
    int tid = threadIdx.x;
    __shared__ float s_red[8];
    float s = 0.f;
    for (int i = tid; i < N_; i += 256)
        s += log1pf(g_neg[i] / g_pos[i]);
    s = warp_sum(s);
    if ((tid & 31) == 0) s_red[tid >> 5] = s;
    __syncthreads();
    if (tid == 0) {
        float t = 0.f;
        #pragma unroll
        for (int w = 0; w < 8; ++w) t += s_red[w];
        out[loss_idx] = t / (float)N_;
    }
}

// ---------------- launch ----------------
extern "C" void kernel_launch(void* const* d_in, const int* in_sizes, int n_in,
                              void* d_out, int out_size) {
    const float* rep    = (const float*)d_in[0];
    const float* aug    = (const float*)d_in[1];
    const float* rel    = (const float*)d_in[2];
    const float* cls_w  = (const float*)d_in[3];
    const float* cls_b  = (const float*)d_in[4];
    const int*   labels = (const int*)d_in[5];
    const float* temp   = (const float*)d_in[6];
    float* out = (float*)d_out;

    static bool attr_set = false;
    if (!attr_set) {
        cudaFuncSetAttribute(k_pair_hmma, cudaFuncAttributeMaxDynamicSharedMemorySize, PAIR_SMEM);
        attr_set = true;
    }

    k_zero<<<(N_ + 255) / 256, 256>>>();
    k_bag<<<B_, 256>>>(rep, aug, rel, labels, temp);
    k_clsout<<<B_, 256>>>(cls_w, cls_b, out);
    dim3 g3(N_ / 128, B_ / 128);   // (128, 4)
    k_pair_hmma<<<g3, 256, PAIR_SMEM>>>(temp);
    k_loss<<<1, 256>>>(out, out_size - 1);
}

// round 4
// speedup vs baseline: 4.6760x; 1.2000x over previous
#include <cuda_runtime.h>
#include <cuda_bf16.h>

#define B_    512
#define BAG_  32
#define H_    1024
#define C_    53
#define N_    (B_*BAG_)   // 16384
#define EPS_  1e-8f
#define NSLOT 16

// ---------------- device scratch ----------------
// chunked+pre-swizzled bf16 layouts for the pair GEMM:
// elem(n,k): chunk kc=k>>6, byte = kc*(ROWS*128) + (n>>3)*1024 + sw128((n&7)*128 + (k&63)*2)
__device__ __align__(128) __nv_bfloat16 g_rep_bf[N_*H_];
__device__ __align__(128) __nv_bfloat16 g_bag_bf[B_*H_];
__device__ float g_bag[B_*H_];      // bag_reps fp32 (classifier)
__device__ float g_rnb[B_];         // 1/||bag||
__device__ float g_rnr[N_];         // 1/||rep||
__device__ float g_pos[N_];         // exp(pos_sim/T)
__device__ float g_negp[NSLOT][N_]; // contention-split neg accumulators
__device__ float g_lsum;
__device__ int   g_cnt = 0;

__device__ __forceinline__ float warp_sum(float v) {
    #pragma unroll
    for (int o = 16; o; o >>= 1) v += __shfl_down_sync(0xffffffffu, v, o);
    return v;
}
__device__ __forceinline__ float warp_max(float v) {
    #pragma unroll
    for (int o = 16; o; o >>= 1) v = fmaxf(v, __shfl_xor_sync(0xffffffffu, v, o));
    return v;
}

// ---------------- PTX helpers (baseline sm_103, no 'a' features) ----------
#define MBAR_INIT(addr, cnt) \
    asm volatile("mbarrier.init.shared.b64 [%0], %1;" :: "r"(addr), "r"(cnt) : "memory")

#define MBAR_WAIT(addr, par) do {                                              \
    unsigned _m = (addr), _p = (par), _d;                                      \
    asm volatile("{\n\t.reg .pred p;\n\t"                                      \
        "mbarrier.try_wait.parity.acquire.cta.shared::cta.b64 p, [%1], %2;\n\t"\
        "selp.b32 %0,1,0,p;\n\t}" : "=r"(_d) : "r"(_m), "r"(_p) : "memory");   \
    if (!_d) {                                                                 \
        asm volatile("{\n\t.reg .pred P1;\n\t"                                 \
        "WL_%=:\n\t"                                                           \
        "mbarrier.try_wait.parity.acquire.cta.shared::cta.b64 P1, [%0], %1, 0x989680;\n\t" \
        "@P1 bra.uni WD_%=;\n\t"                                               \
        "bra.uni WL_%=;\n\t"                                                   \
        "WD_%=:\n\t}" :: "r"(_m), "r"(_p) : "memory");                         \
    }                                                                          \
} while (0)

#define MBAR_ARRIVE(addr) \
    asm volatile("mbarrier.arrive.shared.b64 _, [%0];" :: "r"(addr) : "memory")

#define LDSM4(r, addr) \
    asm volatile("ldmatrix.sync.aligned.m8n8.x4.shared.b16 {%0,%1,%2,%3}, [%4];" \
        : "=r"((r)[0]), "=r"((r)[1]), "=r"((r)[2]), "=r"((r)[3]) : "r"(addr))

#define MMA_BF16(c, a, b0v, b1v) \
    asm volatile("mma.sync.aligned.m16n8k16.row.col.f32.bf16.bf16.f32 " \
        "{%0,%1,%2,%3}, {%4,%5,%6,%7}, {%8,%9}, {%0,%1,%2,%3};" \
        : "+f"((c)[0]), "+f"((c)[1]), "+f"((c)[2]), "+f"((c)[3]) \
        : "r"((a)[0]), "r"((a)[1]), "r"((a)[2]), "r"((a)[3]), "r"(b0v), "r"(b1v))

__device__ __forceinline__ void bulk_cp(unsigned dst, const void* src,
                                        unsigned bytes, unsigned mbar) {
    asm volatile(
        "cp.async.bulk.shared::cta.global.mbarrier::complete_tx::bytes [%0], [%1], %2, [%3];"
        :: "r"(dst), "l"(src), "r"(bytes), "r"(mbar) : "memory");
}
__device__ __forceinline__ void mbar_expect(unsigned mbar, unsigned bytes) {
    asm volatile("mbarrier.arrive.expect_tx.shared.b64 _, [%0], %1;"
                 :: "r"(mbar), "r"(bytes) : "memory");
}
__device__ __forceinline__ unsigned sw128(unsigned byo) {
    return byo ^ ((byo >> 3) & 0x70);
}
__device__ __forceinline__ unsigned bf2u(__nv_bfloat162 h) {
    return *(unsigned*)&h;
}

// ---------------- K1: attention pooling + norms + pos + bf16 staging -------
__global__ void __launch_bounds__(256) k_bag(
    const float* __restrict__ rep, const float* __restrict__ aug,
    const float* __restrict__ rel_table, const int* __restrict__ labels,
    const float* __restrict__ tptr)
{
    int b = blockIdx.x;
    int tid = threadIdx.x, wid = tid >> 5, lane = tid & 31;
    const float* repb = rep + (size_t)b * BAG_ * H_;
    const float* augb = aug + (size_t)b * BAG_ * H_;
    const float4* rel4 = (const float4*)(rel_table + (size_t)labels[b] * H_);
    float invT = 1.0f / tptr[0];

    // zero the neg slot accumulators for this sample + loss scalar
    #pragma unroll
    for (int q = 0; q < 2; ++q)
        g_negp[wid + q * 8][b * BAG_ + lane] = 0.0f;
    if (b == 0 && tid == 0) g_lsum = 0.0f;

    __shared__ float s_scores[BAG_];
    __shared__ float s_alpha[BAG_];
    __shared__ float s_red[8];

    // each warp: 4 sentences (float4 streams)
    for (int j = wid; j < BAG_; j += 8) {
        const float4* r4 = (const float4*)(repb + (size_t)j * H_);
        const float4* a4 = (const float4*)(augb + (size_t)j * H_);
        int n = b * BAG_ + j;
        char* dstb = (char*)g_rep_bf + (size_t)(n >> 3) * 1024;
        unsigned rowoff = (unsigned)(n & 7) * 128u;
        unsigned inoff  = sw128(rowoff + (unsigned)(lane & 15) * 8u);
        float ds = 0.f, dr = 0.f, da = 0.f, dra = 0.f;
        #pragma unroll
        for (int i = 0; i < 8; ++i) {
            int t = lane + 32 * i;
            float4 rv = r4[t], av = a4[t], rl = rel4[t];
            uint2 pk;
            pk.x = bf2u(__floats2bfloat162_rn(rv.x, rv.y));
            pk.y = bf2u(__floats2bfloat162_rn(rv.z, rv.w));
            unsigned kc = (unsigned)(lane >> 4) + 2u * i;
            *(uint2*)(dstb + (size_t)kc * (N_ * 128) + inoff) = pk;
            ds  = fmaf(rl.x, rv.x, fmaf(rl.y, rv.y, fmaf(rl.z, rv.z, fmaf(rl.w, rv.w, ds))));
            dr  = fmaf(rv.x, rv.x, fmaf(rv.y, rv.y, fmaf(rv.z, rv.z, fmaf(rv.w, rv.w, dr))));
            da  = fmaf(av.x, av.x, fmaf(av.y, av.y, fmaf(av.z, av.z, fmaf(av.w, av.w, da))));
            dra = fmaf(rv.x, av.x, fmaf(rv.y, av.y, fmaf(rv.z, av.z, fmaf(rv.w, av.w, dra))));
        }
        ds = warp_sum(ds); dr = warp_sum(dr); da = warp_sum(da); dra = warp_sum(dra);
        if (lane == 0) {
            s_scores[j] = ds * (1.0f / 32.0f);          // / sqrt(H)
            float nr = sqrtf(dr), na = sqrtf(da);
            g_rnr[n] = 1.0f / nr;
            float psim = dra / fmaxf(nr * na, EPS_);
            g_pos[n] = expf(psim * invT);
        }
    }
    __syncthreads();

    if (tid < 32) {
        float v = s_scores[tid];
        float m = warp_max(v);
        float e = expf(v - m);
        float s = warp_sum(e);
        s = __shfl_sync(0xffffffffu, s, 0);
        s_alpha[tid] = e / s;
    }
    __syncthreads();

    // pooling: one float4 per thread (h = tid*4 .. tid*4+3)
    const float4* rp4 = (const float4*)repb;
    float4 acc = make_float4(0.f, 0.f, 0.f, 0.f);
    #pragma unroll 8
    for (int j = 0; j < BAG_; ++j) {
        float4 v = rp4[(size_t)j * 256 + tid];
        float a = s_alpha[j];
        acc.x = fmaf(a, v.x, acc.x); acc.y = fmaf(a, v.y, acc.y);
        acc.z = fmaf(a, v.z, acc.z); acc.w = fmaf(a, v.w, acc.w);
    }
    ((float4*)g_bag)[(size_t)b * 256 + tid] = acc;
    {
        uint2 pk;
        pk.x = bf2u(__floats2bfloat162_rn(acc.x, acc.y));
        pk.y = bf2u(__floats2bfloat162_rn(acc.z, acc.w));
        unsigned kc = (unsigned)tid >> 4;
        unsigned sw = sw128((unsigned)(b & 7) * 128u + (unsigned)(tid & 15) * 8u);
        *(uint2*)((char*)g_bag_bf + (size_t)kc * (B_ * 128) + (size_t)(b >> 3) * 1024 + sw) = pk;
    }
    float nb_part = fmaf(acc.x, acc.x, fmaf(acc.y, acc.y, fmaf(acc.z, acc.z, acc.w * acc.w)));
    nb_part = warp_sum(nb_part);
    if (lane == 0) s_red[wid] = nb_part;
    __syncthreads();
    if (tid == 0) {
        float s = 0.f;
        #pragma unroll
        for (int w = 0; w < 8; ++w) s += s_red[w];
        g_rnb[b] = 1.0f / sqrtf(s);
    }
}

// ---------------- K2: classifier, 64 blocks x 8 bag rows -------------------
__global__ void __launch_bounds__(256) k_clsout(
    const float* __restrict__ cls_w, const float* __restrict__ cls_b,
    float* __restrict__ out)
{
    __shared__ float4 sbag[8][256];     // 8 rows x 1024 fp32 = 32 KB
    int tid = threadIdx.x, wid = tid >> 5, lane = tid & 31;
    int b0 = blockIdx.x * 8;
    for (int idx = tid; idx < 2048; idx += 256)
        sbag[idx >> 8][idx & 255] =
            ((const float4*)g_bag)[(size_t)(b0 + (idx >> 8)) * 256 + (idx & 255)];
    __syncthreads();

    for (int c0 = wid * 2; c0 < C_; c0 += 16) {
        int c1 = c0 + 1;
        bool has1 = c1 < C_;
        const float4* w0 = (const float4*)(cls_w + (size_t)c0 * H_);
        const float4* w1 = (const float4*)(cls_w + (size_t)(has1 ? c1 : c0) * H_);
        float acc0[8] = {}, acc1[8] = {};
        for (int i = lane; i < 256; i += 32) {
            float4 wa = w0[i], wb = w1[i];
            #pragma unroll
            for (int r = 0; r < 8; ++r) {
                float4 v = sbag[r][i];
                acc0[r] = fmaf(wa.x, v.x, fmaf(wa.y, v.y, fmaf(wa.z, v.z, fmaf(wa.w, v.w, acc0[r]))));
                acc1[r] = fmaf(wb.x, v.x, fmaf(wb.y, v.y, fmaf(wb.z, v.z, fmaf(wb.w, v.w, acc1[r]))));
            }
        }
        #pragma unroll
        for (int r = 0; r < 8; ++r) {
            float s0 = warp_sum(acc0[r]);
            float s1 = warp_sum(acc1[r]);
            if (lane == 0) {
                out[(b0 + r) * C_ + c0] = s0 + cls_b[c0];
                if (has1) out[(b0 + r) * C_ + c1] = s1 + cls_b[c1];
            }
        }
    }
}

// ---------------- K3: bf16 HMMA pair GEMM, full/empty mbarrier ring --------
#define STAGES 3
#define STAGE_BYTES 32768
#define NKC 16
#define PAIR_SMEM (STAGES * STAGE_BYTES)   // 98304

__global__ void __launch_bounds__(256, 2) k_pair_hmma(const float* __restrict__ tptr)
{
    extern __shared__ __align__(16) char smem[];
    __shared__ __align__(8) unsigned long long mbars[2 * STAGES]; // full[0..2], empty[3..5]
    unsigned smem_u = (unsigned)__cvta_generic_to_shared(smem);
    unsigned mbar_u = (unsigned)__cvta_generic_to_shared(mbars);
    int tid = threadIdx.x, wid = tid >> 5, lane = tid & 31;
    int wm = wid >> 2, wn = wid & 3;
    int m0 = blockIdx.y * 128, n0 = blockIdx.x * 128;

    if (tid == 0) {
        #pragma unroll
        for (int s = 0; s < STAGES; ++s) {
            MBAR_INIT(mbar_u + 8 * s, 1);              // full: tx-based
            MBAR_INIT(mbar_u + 8 * (STAGES + s), 8);   // empty: 1 arrive per warp
        }
    }
    __syncthreads();

    const char* Asrc = (const char*)g_bag_bf;
    const char* Bsrc = (const char*)g_rep_bf;
    if (tid == 0) {
        #pragma unroll
        for (int s = 0; s < STAGES; ++s) {
            unsigned mb = mbar_u + 8 * s;
            mbar_expect(mb, 2 * 16384u);
            unsigned d = smem_u + s * STAGE_BYTES;
            bulk_cp(d,          Asrc + ((size_t)s * B_ + m0) * 128, 16384u, mb);
            bulk_cp(d + 16384u, Bsrc + ((size_t)s * N_ + n0) * 128, 16384u, mb);
        }
    }

    unsigned xr   = (unsigned)(lane & 7) * 16u;
    unsigned hk16 = (unsigned)(lane >> 4) * 16u;
    unsigned kb16 = (unsigned)((lane >> 3) & 1) * 16u;
    unsigned aoffb = (unsigned)((wm * 64 + (lane & 15)) * 128);
    unsigned boffb = (unsigned)((wn * 32 + ((lane >> 4) & 1) * 8 + (lane & 7)) * 128) + 16384u;

    float acc[4][4][4] = {};

    #pragma unroll 1
    for (int kc = 0; kc < NKC; ++kc) {
        int st = kc % 3;
        unsigned u = (unsigned)(kc / 3);
        MBAR_WAIT(mbar_u + 8 * st, u & 1);
        unsigned base = smem_u + st * STAGE_BYTES;
        #pragma unroll
        for (int ks = 0; ks < 4; ++ks) {
            unsigned afr[4][4], bfr[2][4];
            unsigned ksa = ((unsigned)(ks * 32) + hk16) ^ xr;
            unsigned ksb = ((unsigned)(ks * 32) + kb16) ^ xr;
            #pragma unroll
            for (int mt = 0; mt < 4; ++mt)
                LDSM4(afr[mt], base + aoffb + mt * 2048u + ksa);
            #pragma unroll
            for (int np = 0; np < 2; ++np)
                LDSM4(bfr[np], base + boffb + np * 2048u + ksb);
            #pragma unroll
            for (int mt = 0; mt < 4; ++mt)
                #pragma unroll
                for (int nt = 0; nt < 4; ++nt)
                    MMA_BF16(acc[mt][nt], afr[mt],
                             bfr[nt >> 1][(nt & 1) * 2], bfr[nt >> 1][(nt & 1) * 2 + 1]);
        }
        // per-warp arrival: this warp is done reading stage st for use u
        if (lane == 0) MBAR_ARRIVE(mbar_u + 8 * (STAGES + st));
        // producer: refill stage st for use u+1 once all 8 warps arrived
        if (tid == 0 && kc + STAGES < NKC) {
            MBAR_WAIT(mbar_u + 8 * (STAGES + st), u & 1);
            unsigned mb = mbar_u + 8 * st;
            mbar_expect(mb, 2 * 16384u);
            unsigned d = smem_u + st * STAGE_BYTES;
            bulk_cp(d,          Asrc + ((size_t)(kc + STAGES) * B_ + m0) * 128, 16384u, mb);
            bulk_cp(d + 16384u, Bsrc + ((size_t)(kc + STAGES) * N_ + n0) * 128, 16384u, mb);
        }
    }
    __syncthreads();   // all warps done with all stages before smem reuse

    // ---- epilogue: exp + diagonal skip, 4-pass smem reduce, slotted atomics --
    float* sbuf  = (float*)smem;                    // [128][34]
    float* s_rnr = (float*)(smem + 17408);
    float* s_rnb = (float*)(smem + 17408 + 512);
    if (tid < 128) { s_rnr[tid] = g_rnr[n0 + tid]; s_rnb[tid] = g_rnb[m0 + tid]; }
    __syncthreads();
    float invT = 1.0f / tptr[0];
    int bglob = (n0 >> 5) + wn;
    int r0base = wm * 64 + (lane >> 2);
    float* negslot = g_negp[blockIdx.x & (NSLOT - 1)];

    for (int pass = 0; pass < 4; ++pass) {
        if (wn == pass) {
            #pragma unroll
            for (int mt = 0; mt < 4; ++mt) {
                int r0 = r0base + mt * 16, r1 = r0 + 8;
                float f0 = s_rnb[r0] * invT, f1 = s_rnb[r1] * invT;
                bool sk0 = (m0 + r0) == bglob, sk1 = (m0 + r1) == bglob;
                #pragma unroll
                for (int nt = 0; nt < 4; ++nt) {
                    int jj = nt * 8 + (lane & 3) * 2;
                    float rn0 = s_rnr[wn * 32 + jj], rn1 = s_rnr[wn * 32 + jj + 1];
                    float e00 = sk0 ? 0.f : __expf(acc[mt][nt][0] * f0 * rn0);
                    float e01 = sk0 ? 0.f : __expf(acc[mt][nt][1] * f0 * rn1);
                    float e10 = sk1 ? 0.f : __expf(acc[mt][nt][2] * f1 * rn0);
                    float e11 = sk1 ? 0.f : __expf(acc[mt][nt][3] * f1 * rn1);
                    float* p0 = &sbuf[r0 * 34 + jj];
                    float* p1 = &sbuf[r1 * 34 + jj];
                    if (pass == 0) { p0[0] = e00; p0[1] = e01; p1[0] = e10; p1[1] = e11; }
                    else           { p0[0] += e00; p0[1] += e01; p1[0] += e10; p1[1] += e11; }
                }
            }
        }
        __syncthreads();
    }
    for (int e = tid; e < 4096; e += 256) {
        int lc = e >> 5, jj = e & 31;
        atomicAdd(&negslot[(m0 + lc) * BAG_ + jj], sbuf[lc * 34 + jj]);
    }
}

// ---------------- K4: loss (grid-parallel, last block finalizes) -----------
__global__ void __launch_bounds__(256) k_loss(const float* __restrict__ pos,
                                              float* __restrict__ out, int loss_idx) {
    int i = blockIdx.x * 256 + threadIdx.x;
    float t = 0.f;
    #pragma unroll
    for (int s = 0; s < NSLOT; ++s) t += g_negp[s][i];
    float v = __logf(1.0f + __fdividef(t, pos[i]));
    v = warp_sum(v);
    __shared__ float sr[8];
    if ((threadIdx.x & 31) == 0) sr[threadIdx.x >> 5] = v;
    __syncthreads();
    if (threadIdx.x == 0) {
        float s = 0.f;
        #pragma unroll
        for (int w = 0; w < 8; ++w) s += sr[w];
        atomicAdd(&g_lsum, s);
        __threadfence();
        if (atomicAdd(&g_cnt, 1) == (N_ / 256) - 1) {
            out[loss_idx] = g_lsum * (1.0f / (float)N_);
            g_cnt = 0;
        }
    }
}

// ---------------- launch ----------------
extern "C" void kernel_launch(void* const* d_in, const int* in_sizes, int n_in,
                              void* d_out, int out_size) {
    const float* rep    = (const float*)d_in[0];
    const float* aug    = (const float*)d_in[1];
    const float* rel    = (const float*)d_in[2];
    const float* cls_w  = (const float*)d_in[3];
    const float* cls_b  = (const float*)d_in[4];
    const int*   labels = (const int*)d_in[5];
    const float* temp   = (const float*)d_in[6];
    float* out = (float*)d_out;

    static bool attr_set = false;
    if (!attr_set) {
        cudaFuncSetAttribute(k_pair_hmma, cudaFuncAttributeMaxDynamicSharedMemorySize, PAIR_SMEM);
        attr_set = true;
    }

    k_bag<<<B_, 256>>>(rep, aug, rel, labels, temp);
    k_clsout<<<B_ / 8, 256>>>(cls_w, cls_b, out);
    dim3 g3(N_ / 128, B_ / 128);   // (128, 4)
    k_pair_hmma<<<g3, 256, PAIR_SMEM>>>(temp);

    float* g_pos_ptr = nullptr;
    cudaGetSymbolAddress((void**)&g_pos_ptr, g_pos);
    k_loss<<<N_ / 256, 256>>>(g_pos_ptr, out, out_size - 1);
}

// round 5
// speedup vs baseline: 4.9326x; 1.0549x over previous
#include <cuda_runtime.h>
#include <cuda_bf16.h>

#define B_    512
#define BAG_  32
#define H_    1024
#define C_    53
#define N_    (B_*BAG_)   // 16384
#define EPS_  1e-8f
#define NSLOT 16

// ---------------- device scratch ----------------
__device__ __align__(128) __nv_bfloat16 g_rep_bf[N_*H_];
__device__ __align__(128) __nv_bfloat16 g_bag_bf[B_*H_];
__device__ float g_bag[B_*H_];
__device__ float g_rnb[B_];
__device__ float g_rnr[N_];
__device__ float g_pos[N_];
__device__ float g_negp[NSLOT][N_];
__device__ float g_lsum;
__device__ int   g_cnt = 0;

__device__ __forceinline__ float warp_sum(float v) {
    #pragma unroll
    for (int o = 16; o; o >>= 1) v += __shfl_down_sync(0xffffffffu, v, o);
    return v;
}
__device__ __forceinline__ float warp_max(float v) {
    #pragma unroll
    for (int o = 16; o; o >>= 1) v = fmaxf(v, __shfl_xor_sync(0xffffffffu, v, o));
    return v;
}

// fast exp on the FMA pipe: no MUFU, no CVT. |x| <= 20, rel err < 3e-6.
__device__ __forceinline__ float fexp(float x) {
    const float LOG2E = 1.4426950408889634f;
    float z = fmaf(x, LOG2E, 12582912.0f);       // 1.5*2^23: round-to-int in mantissa
    int   iz = __float_as_int(z);
    float r  = z - 12582912.0f;
    float f  = fmaf(x, LOG2E, -r);               // f in [-0.5, 0.5]
    float p =            1.3298820e-3f;
    p = fmaf(p, f, 9.6179670e-3f);
    p = fmaf(p, f, 5.5503645e-2f);
    p = fmaf(p, f, 2.4022645e-1f);
    p = fmaf(p, f, 6.9314718e-1f);
    p = fmaf(p, f, 1.0f);
    unsigned sc = ((unsigned)iz + (127u - 0x4B400000u)) << 23;
    return p * __int_as_float(sc);
}

// ---------------- PTX helpers ----------
#define MBAR_INIT(addr, cnt) \
    asm volatile("mbarrier.init.shared.b64 [%0], %1;" :: "r"(addr), "r"(cnt) : "memory")

#define MBAR_WAIT(addr, par) do {                                              \
    unsigned _m = (addr), _p = (par), _d;                                      \
    asm volatile("{\n\t.reg .pred p;\n\t"                                      \
        "mbarrier.try_wait.parity.acquire.cta.shared::cta.b64 p, [%1], %2;\n\t"\
        "selp.b32 %0,1,0,p;\n\t}" : "=r"(_d) : "r"(_m), "r"(_p) : "memory");   \
    if (!_d) {                                                                 \
        asm volatile("{\n\t.reg .pred P1;\n\t"                                 \
        "WL_%=:\n\t"                                                           \
        "mbarrier.try_wait.parity.acquire.cta.shared::cta.b64 P1, [%0], %1, 0x989680;\n\t" \
        "@P1 bra.uni WD_%=;\n\t"                                               \
        "bra.uni WL_%=;\n\t"                                                   \
        "WD_%=:\n\t}" :: "r"(_m), "r"(_p) : "memory");                         \
    }                                                                          \
} while (0)

#define MBAR_ARRIVE(addr) \
    asm volatile("mbarrier.arrive.shared.b64 _, [%0];" :: "r"(addr) : "memory")

#define LDSM4(r, addr) \
    asm volatile("ldmatrix.sync.aligned.m8n8.x4.shared.b16 {%0,%1,%2,%3}, [%4];" \
        : "=r"((r)[0]), "=r"((r)[1]), "=r"((r)[2]), "=r"((r)[3]) : "r"(addr))

#define MMA_BF16(c, a, b0v, b1v) \
    asm volatile("mma.sync.aligned.m16n8k16.row.col.f32.bf16.bf16.f32 " \
        "{%0,%1,%2,%3}, {%4,%5,%6,%7}, {%8,%9}, {%0,%1,%2,%3};" \
        : "+f"((c)[0]), "+f"((c)[1]), "+f"((c)[2]), "+f"((c)[3]) \
        : "r"((a)[0]), "r"((a)[1]), "r"((a)[2]), "r"((a)[3]), "r"(b0v), "r"(b1v))

__device__ __forceinline__ void bulk_cp(unsigned dst, const void* src,
                                        unsigned bytes, unsigned mbar) {
    asm volatile(
        "cp.async.bulk.shared::cta.global.mbarrier::complete_tx::bytes [%0], [%1], %2, [%3];"
        :: "r"(dst), "l"(src), "r"(bytes), "r"(mbar) : "memory");
}
__device__ __forceinline__ void mbar_expect(unsigned mbar, unsigned bytes) {
    asm volatile("mbarrier.arrive.expect_tx.shared.b64 _, [%0], %1;"
                 :: "r"(mbar), "r"(bytes) : "memory");
}
__device__ __forceinline__ unsigned sw128(unsigned byo) {
    return byo ^ ((byo >> 3) & 0x70);
}
__device__ __forceinline__ unsigned bf2u(__nv_bfloat162 h) {
    return *(unsigned*)&h;
}

// ---------------- K1: pooling + norms + pos, rep cached in smem ------------
#define KBAG_SMEM (BAG_ * H_ * 4)   // 131072

__global__ void __launch_bounds__(256) k_bag(
    const float* __restrict__ rep, const float* __restrict__ aug,
    const float* __restrict__ rel_table, const int* __restrict__ labels,
    const float* __restrict__ tptr)
{
    extern __shared__ __align__(16) float srep[];        // [32][1024]
    __shared__ float s_scores[BAG_];
    __shared__ float s_alpha[BAG_];
    __shared__ float s_red[8];
    __shared__ __align__(8) unsigned long long s_mb;

    int b = blockIdx.x;
    int tid = threadIdx.x, wid = tid >> 5, lane = tid & 31;
    const float* repb = rep + (size_t)b * BAG_ * H_;
    const float* augb = aug + (size_t)b * BAG_ * H_;
    const float4* rel4 = (const float4*)(rel_table + (size_t)labels[b] * H_);
    float invT = 1.0f / tptr[0];
    unsigned smem_u = (unsigned)__cvta_generic_to_shared(srep);
    unsigned mbu    = (unsigned)__cvta_generic_to_shared(&s_mb);

    // zero neg slots for this sample; reset loss scalar
    #pragma unroll
    for (int q = 0; q < 2; ++q)
        g_negp[wid + q * 8][b * BAG_ + lane] = 0.0f;
    if (b == 0 && tid == 0) g_lsum = 0.0f;

    if (tid == 0) MBAR_INIT(mbu, 1);
    __syncthreads();
    if (tid == 0) {
        mbar_expect(mbu, (unsigned)KBAG_SMEM);
        bulk_cp(smem_u, repb, (unsigned)KBAG_SMEM, mbu);
    }

    const float4* srep4 = (const float4*)srep;

    // each warp: 4 sentences; aug staged in registers while rep bulk lands
    for (int j = wid; j < BAG_; j += 8) {
        const float4* a4 = (const float4*)(augb + (size_t)j * H_);
        float4 av[8];
        float da = 0.f;
        #pragma unroll
        for (int i = 0; i < 8; ++i) {
            av[i] = a4[lane + 32 * i];
            da = fmaf(av[i].x, av[i].x, fmaf(av[i].y, av[i].y,
                 fmaf(av[i].z, av[i].z, fmaf(av[i].w, av[i].w, da))));
        }
        MBAR_WAIT(mbu, 0);   // rep tile ready (fast-path after first completion)

        int n = b * BAG_ + j;
        char* dstb = (char*)g_rep_bf + (size_t)(n >> 3) * 1024;
        unsigned inoff = sw128((unsigned)(n & 7) * 128u + (unsigned)(lane & 15) * 8u);
        float ds = 0.f, dr = 0.f, dra = 0.f;
        #pragma unroll
        for (int i = 0; i < 8; ++i) {
            int t = lane + 32 * i;
            float4 rv = srep4[j * 256 + t];
            float4 rl = rel4[t];
            uint2 pk;
            pk.x = bf2u(__floats2bfloat162_rn(rv.x, rv.y));
            pk.y = bf2u(__floats2bfloat162_rn(rv.z, rv.w));
            unsigned kc = (unsigned)(lane >> 4) + 2u * i;
            *(uint2*)(dstb + (size_t)kc * (N_ * 128) + inoff) = pk;
            ds  = fmaf(rl.x, rv.x, fmaf(rl.y, rv.y, fmaf(rl.z, rv.z, fmaf(rl.w, rv.w, ds))));
            dr  = fmaf(rv.x, rv.x, fmaf(rv.y, rv.y, fmaf(rv.z, rv.z, fmaf(rv.w, rv.w, dr))));
            dra = fmaf(rv.x, av[i].x, fmaf(rv.y, av[i].y,
                  fmaf(rv.z, av[i].z, fmaf(rv.w, av[i].w, dra))));
        }
        ds = warp_sum(ds); dr = warp_sum(dr); da = warp_sum(da); dra = warp_sum(dra);
        if (lane == 0) {
            s_scores[j] = ds * (1.0f / 32.0f);          // / sqrt(H)
            float nr = sqrtf(dr), na = sqrtf(da);
            g_rnr[n] = 1.0f / nr;
            float psim = dra / fmaxf(nr * na, EPS_);
            g_pos[n] = expf(psim * invT);
        }
    }
    __syncthreads();

    if (tid < 32) {
        float v = s_scores[tid];
        float m = warp_max(v);
        float e = expf(v - m);
        float s = warp_sum(e);
        s = __shfl_sync(0xffffffffu, s, 0);
        s_alpha[tid] = e / s;
    }
    __syncthreads();

    // pooling from smem: one float4 per thread
    float4 acc = make_float4(0.f, 0.f, 0.f, 0.f);
    #pragma unroll 8
    for (int j = 0; j < BAG_; ++j) {
        float4 v = srep4[j * 256 + tid];
        float a = s_alpha[j];
        acc.x = fmaf(a, v.x, acc.x); acc.y = fmaf(a, v.y, acc.y);
        acc.z = fmaf(a, v.z, acc.z); acc.w = fmaf(a, v.w, acc.w);
    }
    ((float4*)g_bag)[(size_t)b * 256 + tid] = acc;
    {
        uint2 pk;
        pk.x = bf2u(__floats2bfloat162_rn(acc.x, acc.y));
        pk.y = bf2u(__floats2bfloat162_rn(acc.z, acc.w));
        unsigned kc = (unsigned)tid >> 4;
        unsigned sw = sw128((unsigned)(b & 7) * 128u + (unsigned)(tid & 15) * 8u);
        *(uint2*)((char*)g_bag_bf + (size_t)kc * (B_ * 128) + (size_t)(b >> 3) * 1024 + sw) = pk;
    }
    float nb_part = fmaf(acc.x, acc.x, fmaf(acc.y, acc.y, fmaf(acc.z, acc.z, acc.w * acc.w)));
    nb_part = warp_sum(nb_part);
    if (lane == 0) s_red[wid] = nb_part;
    __syncthreads();
    if (tid == 0) {
        float s = 0.f;
        #pragma unroll
        for (int w = 0; w < 8; ++w) s += s_red[w];
        g_rnb[b] = 1.0f / sqrtf(s);
    }
}

// ---------------- K2: classifier, 64 blocks x 8 bag rows -------------------
__global__ void __launch_bounds__(256) k_clsout(
    const float* __restrict__ cls_w, const float* __restrict__ cls_b,
    float* __restrict__ out)
{
    __shared__ float4 sbag[8][256];
    int tid = threadIdx.x, wid = tid >> 5, lane = tid & 31;
    int b0 = blockIdx.x * 8;
    for (int idx = tid; idx < 2048; idx += 256)
        sbag[idx >> 8][idx & 255] =
            ((const float4*)g_bag)[(size_t)(b0 + (idx >> 8)) * 256 + (idx & 255)];
    __syncthreads();

    for (int c0 = wid * 2; c0 < C_; c0 += 16) {
        int c1 = c0 + 1;
        bool has1 = c1 < C_;
        const float4* w0 = (const float4*)(cls_w + (size_t)c0 * H_);
        const float4* w1 = (const float4*)(cls_w + (size_t)(has1 ? c1 : c0) * H_);
        float acc0[8] = {}, acc1[8] = {};
        for (int i = lane; i < 256; i += 32) {
            float4 wa = w0[i], wb = w1[i];
            #pragma unroll
            for (int r = 0; r < 8; ++r) {
                float4 v = sbag[r][i];
                acc0[r] = fmaf(wa.x, v.x, fmaf(wa.y, v.y, fmaf(wa.z, v.z, fmaf(wa.w, v.w, acc0[r]))));
                acc1[r] = fmaf(wb.x, v.x, fmaf(wb.y, v.y, fmaf(wb.z, v.z, fmaf(wb.w, v.w, acc1[r]))));
            }
        }
        #pragma unroll
        for (int r = 0; r < 8; ++r) {
            float s0 = warp_sum(acc0[r]);
            float s1 = warp_sum(acc1[r]);
            if (lane == 0) {
                out[(b0 + r) * C_ + c0] = s0 + cls_b[c0];
                if (has1) out[(b0 + r) * C_ + c1] = s1 + cls_b[c1];
            }
        }
    }
}

// ---------------- K3: bf16 HMMA pair GEMM + FMA-exp epilogue ---------------
#define STAGES 3
#define STAGE_BYTES 32768
#define NKC 16
#define PAIR_SMEM (STAGES * STAGE_BYTES)   // 98304

__global__ void __launch_bounds__(256, 2) k_pair_hmma(const float* __restrict__ tptr)
{
    extern __shared__ __align__(16) char smem[];
    __shared__ __align__(8) unsigned long long mbars[2 * STAGES];
    unsigned smem_u = (unsigned)__cvta_generic_to_shared(smem);
    unsigned mbar_u = (unsigned)__cvta_generic_to_shared(mbars);
    int tid = threadIdx.x, wid = tid >> 5, lane = tid & 31;
    int wm = wid >> 2, wn = wid & 3;
    int m0 = blockIdx.y * 128, n0 = blockIdx.x * 128;

    if (tid == 0) {
        #pragma unroll
        for (int s = 0; s < STAGES; ++s) {
            MBAR_INIT(mbar_u + 8 * s, 1);
            MBAR_INIT(mbar_u + 8 * (STAGES + s), 8);
        }
    }
    __syncthreads();

    const char* Asrc = (const char*)g_bag_bf;
    const char* Bsrc = (const char*)g_rep_bf;
    if (tid == 0) {
        #pragma unroll
        for (int s = 0; s < STAGES; ++s) {
            unsigned mb = mbar_u + 8 * s;
            mbar_expect(mb, 2 * 16384u);
            unsigned d = smem_u + s * STAGE_BYTES;
            bulk_cp(d,          Asrc + ((size_t)s * B_ + m0) * 128, 16384u, mb);
            bulk_cp(d + 16384u, Bsrc + ((size_t)s * N_ + n0) * 128, 16384u, mb);
        }
    }

    unsigned xr   = (unsigned)(lane & 7) * 16u;
    unsigned hk16 = (unsigned)(lane >> 4) * 16u;
    unsigned kb16 = (unsigned)((lane >> 3) & 1) * 16u;
    unsigned aoffb = (unsigned)((wm * 64 + (lane & 15)) * 128);
    unsigned boffb = (unsigned)((wn * 32 + ((lane >> 4) & 1) * 8 + (lane & 7)) * 128) + 16384u;

    float acc[4][4][4] = {};

    #pragma unroll 1
    for (int kc = 0; kc < NKC; ++kc) {
        int st = kc % 3;
        unsigned u = (unsigned)(kc / 3);
        MBAR_WAIT(mbar_u + 8 * st, u & 1);
        unsigned base = smem_u + st * STAGE_BYTES;
        #pragma unroll
        for (int ks = 0; ks < 4; ++ks) {
            unsigned afr[4][4], bfr[2][4];
            unsigned ksa = ((unsigned)(ks * 32) + hk16) ^ xr;
            unsigned ksb = ((unsigned)(ks * 32) + kb16) ^ xr;
            #pragma unroll
            for (int mt = 0; mt < 4; ++mt)
                LDSM4(afr[mt], base + aoffb + mt * 2048u + ksa);
            #pragma unroll
            for (int np = 0; np < 2; ++np)
                LDSM4(bfr[np], base + boffb + np * 2048u + ksb);
            #pragma unroll
            for (int mt = 0; mt < 4; ++mt)
                #pragma unroll
                for (int nt = 0; nt < 4; ++nt)
                    MMA_BF16(acc[mt][nt], afr[mt],
                             bfr[nt >> 1][(nt & 1) * 2], bfr[nt >> 1][(nt & 1) * 2 + 1]);
        }
        if (lane == 0) MBAR_ARRIVE(mbar_u + 8 * (STAGES + st));
        if (tid == 0 && kc + STAGES < NKC) {
            MBAR_WAIT(mbar_u + 8 * (STAGES + st), u & 1);
            unsigned mb = mbar_u + 8 * st;
            mbar_expect(mb, 2 * 16384u);
            unsigned d = smem_u + st * STAGE_BYTES;
            bulk_cp(d,          Asrc + ((size_t)(kc + STAGES) * B_ + m0) * 128, 16384u, mb);
            bulk_cp(d + 16384u, Bsrc + ((size_t)(kc + STAGES) * N_ + n0) * 128, 16384u, mb);
        }
    }
    __syncthreads();

    // ---- epilogue: FMA-pipe exp, single-pass smem reduce, slotted atomics ----
    float* sbuf  = (float*)smem;                    // [4][128][33] = 67584 B
    float* s_rnr = (float*)(smem + 67584);
    float* s_rnb = (float*)(smem + 67584 + 512);
    if (tid < 128) { s_rnr[tid] = g_rnr[n0 + tid]; s_rnb[tid] = g_rnb[m0 + tid]; }
    __syncthreads();
    float invT = 1.0f / tptr[0];
    int bglob = (n0 >> 5) + wn;
    int r0base = wm * 64 + (lane >> 2);
    float* negslot = g_negp[blockIdx.x & (NSLOT - 1)];
    float* wbuf = sbuf + wn * (128 * 33);

    #pragma unroll
    for (int mt = 0; mt < 4; ++mt) {
        int r0 = r0base + mt * 16, r1 = r0 + 8;
        float f0 = s_rnb[r0] * invT, f1 = s_rnb[r1] * invT;
        bool sk0 = (m0 + r0) == bglob, sk1 = (m0 + r1) == bglob;
        #pragma unroll
        for (int nt = 0; nt < 4; ++nt) {
            int jj = nt * 8 + (lane & 3) * 2;
            float rn0 = s_rnr[wn * 32 + jj], rn1 = s_rnr[wn * 32 + jj + 1];
            float e00 = sk0 ? 0.f : fexp(acc[mt][nt][0] * f0 * rn0);
            float e01 = sk0 ? 0.f : fexp(acc[mt][nt][1] * f0 * rn1);
            float e10 = sk1 ? 0.f : fexp(acc[mt][nt][2] * f1 * rn0);
            float e11 = sk1 ? 0.f : fexp(acc[mt][nt][3] * f1 * rn1);
            wbuf[r0 * 33 + jj]     = e00;
            wbuf[r0 * 33 + jj + 1] = e01;
            wbuf[r1 * 33 + jj]     = e10;
            wbuf[r1 * 33 + jj + 1] = e11;
        }
    }
    __syncthreads();
    for (int e = tid; e < 4096; e += 256) {
        int lc = e >> 5, jj = e & 31;
        float v = sbuf[lc * 33 + jj]
                + sbuf[1 * (128 * 33) + lc * 33 + jj]
                + sbuf[2 * (128 * 33) + lc * 33 + jj]
                + sbuf[3 * (128 * 33) + lc * 33 + jj];
        atomicAdd(&negslot[(m0 + lc) * BAG_ + jj], v);
    }
}

// ---------------- K4: loss (grid-parallel, last block finalizes) -----------
__global__ void __launch_bounds__(256) k_loss(const float* __restrict__ pos,
                                              float* __restrict__ out, int loss_idx) {
    int i4 = blockIdx.x * 256 + threadIdx.x;       // float4 index
    float4 t = make_float4(0.f, 0.f, 0.f, 0.f);
    #pragma unroll
    for (int s = 0; s < NSLOT; ++s) {
        float4 v = ((const float4*)g_negp[s])[i4];
        t.x += v.x; t.y += v.y; t.z += v.z; t.w += v.w;
    }
    float4 p = ((const float4*)pos)[i4];
    float v = __logf(1.0f + __fdividef(t.x, p.x))
            + __logf(1.0f + __fdividef(t.y, p.y))
            + __logf(1.0f + __fdividef(t.z, p.z))
            + __logf(1.0f + __fdividef(t.w, p.w));
    v = warp_sum(v);
    __shared__ float sr[8];
    if ((threadIdx.x & 31) == 0) sr[threadIdx.x >> 5] = v;
    __syncthreads();
    if (threadIdx.x == 0) {
        float s = 0.f;
        #pragma unroll
        for (int w = 0; w < 8; ++w) s += sr[w];
        atomicAdd(&g_lsum, s);
        __threadfence();
        if (atomicAdd(&g_cnt, 1) == (N_ / 1024) - 1) {
            out[loss_idx] = g_lsum * (1.0f / (float)N_);
            g_cnt = 0;
        }
    }
}

// ---------------- launch ----------------
extern "C" void kernel_launch(void* const* d_in, const int* in_sizes, int n_in,
                              void* d_out, int out_size) {
    const float* rep    = (const float*)d_in[0];
    const float* aug    = (const float*)d_in[1];
    const float* rel    = (const float*)d_in[2];
    const float* cls_w  = (const float*)d_in[3];
    const float* cls_b  = (const float*)d_in[4];
    const int*   labels = (const int*)d_in[5];
    const float* temp   = (const float*)d_in[6];
    float* out = (float*)d_out;

    static bool attr_set = false;
    if (!attr_set) {
        cudaFuncSetAttribute(k_pair_hmma, cudaFuncAttributeMaxDynamicSharedMemorySize, PAIR_SMEM);
        cudaFuncSetAttribute(k_bag, cudaFuncAttributeMaxDynamicSharedMemorySize, KBAG_SMEM);
        attr_set = true;
    }

    k_bag<<<B_, 256, KBAG_SMEM>>>(rep, aug, rel, labels, temp);
    k_clsout<<<B_ / 8, 256>>>(cls_w, cls_b, out);
    dim3 g3(N_ / 128, B_ / 128);   // (128, 4)
    k_pair_hmma<<<g3, 256, PAIR_SMEM>>>(temp);

    float* g_pos_ptr = nullptr;
    cudaGetSymbolAddress((void**)&g_pos_ptr, g_pos);
    k_loss<<<N_ / 1024, 256>>>(g_pos_ptr, out, out_size - 1);
}

// round 6
// speedup vs baseline: 6.3056x; 1.2784x over previous
#include <cuda_runtime.h>
#include <cuda_bf16.h>

#define B_    512
#define BAG_  32
#define H_    1024
#define C_    53
#define N_    (B_*BAG_)   // 16384
#define EPS_  1e-8f
#define NSLOT 16

// ---------------- device scratch ----------------
__device__ __align__(128) __nv_bfloat16 g_rep_bf[N_*H_];
__device__ __align__(128) __nv_bfloat16 g_bag_bf[B_*H_];
__device__ float g_bag[B_*H_];
__device__ float g_rnb[B_];
__device__ float g_rnr[N_];
__device__ float g_pos[N_];
__device__ float g_negp[NSLOT][N_];
__device__ float g_lsum;
__device__ int   g_cnt = 0;

__device__ __forceinline__ float warp_sum(float v) {
    #pragma unroll
    for (int o = 16; o; o >>= 1) v += __shfl_down_sync(0xffffffffu, v, o);
    return v;
}
__device__ __forceinline__ float warp_max(float v) {
    #pragma unroll
    for (int o = 16; o; o >>= 1) v = fmaxf(v, __shfl_xor_sync(0xffffffffu, v, o));
    return v;
}

// fast exp on the FMA pipe: no MUFU, no CVT. |x| <= 20, rel err < 3e-6.
__device__ __forceinline__ float fexp(float x) {
    const float LOG2E = 1.4426950408889634f;
    float z = fmaf(x, LOG2E, 12582912.0f);
    int   iz = __float_as_int(z);
    float r  = z - 12582912.0f;
    float f  = fmaf(x, LOG2E, -r);
    float p =            1.3298820e-3f;
    p = fmaf(p, f, 9.6179670e-3f);
    p = fmaf(p, f, 5.5503645e-2f);
    p = fmaf(p, f, 2.4022645e-1f);
    p = fmaf(p, f, 6.9314718e-1f);
    p = fmaf(p, f, 1.0f);
    unsigned sc = ((unsigned)iz + (127u - 0x4B400000u)) << 23;
    return p * __int_as_float(sc);
}

// ---------------- PTX helpers ----------
#define MBAR_INIT(addr, cnt) \
    asm volatile("mbarrier.init.shared.b64 [%0], %1;" :: "r"(addr), "r"(cnt) : "memory")

#define MBAR_WAIT(addr, par) do {                                              \
    unsigned _m = (addr), _p = (par), _d;                                      \
    asm volatile("{\n\t.reg .pred p;\n\t"                                      \
        "mbarrier.try_wait.parity.acquire.cta.shared::cta.b64 p, [%1], %2;\n\t"\
        "selp.b32 %0,1,0,p;\n\t}" : "=r"(_d) : "r"(_m), "r"(_p) : "memory");   \
    if (!_d) {                                                                 \
        asm volatile("{\n\t.reg .pred P1;\n\t"                                 \
        "WL_%=:\n\t"                                                           \
        "mbarrier.try_wait.parity.acquire.cta.shared::cta.b64 P1, [%0], %1, 0x989680;\n\t" \
        "@P1 bra.uni WD_%=;\n\t"                                               \
        "bra.uni WL_%=;\n\t"                                                   \
        "WD_%=:\n\t}" :: "r"(_m), "r"(_p) : "memory");                         \
    }                                                                          \
} while (0)

#define MBAR_ARRIVE(addr) \
    asm volatile("mbarrier.arrive.shared.b64 _, [%0];" :: "r"(addr) : "memory")

#define LDSM4(r, addr) \
    asm volatile("ldmatrix.sync.aligned.m8n8.x4.shared.b16 {%0,%1,%2,%3}, [%4];" \
        : "=r"((r)[0]), "=r"((r)[1]), "=r"((r)[2]), "=r"((r)[3]) : "r"(addr))

#define MMA_BF16(c, a, b0v, b1v) \
    asm volatile("mma.sync.aligned.m16n8k16.row.col.f32.bf16.bf16.f32 " \
        "{%0,%1,%2,%3}, {%4,%5,%6,%7}, {%8,%9}, {%0,%1,%2,%3};" \
        : "+f"((c)[0]), "+f"((c)[1]), "+f"((c)[2]), "+f"((c)[3]) \
        : "r"((a)[0]), "r"((a)[1]), "r"((a)[2]), "r"((a)[3]), "r"(b0v), "r"(b1v))

__device__ __forceinline__ void bulk_cp(unsigned dst, const void* src,
                                        unsigned bytes, unsigned mbar) {
    asm volatile(
        "cp.async.bulk.shared::cta.global.mbarrier::complete_tx::bytes [%0], [%1], %2, [%3];"
        :: "r"(dst), "l"(src), "r"(bytes), "r"(mbar) : "memory");
}
__device__ __forceinline__ void mbar_expect(unsigned mbar, unsigned bytes) {
    asm volatile("mbarrier.arrive.expect_tx.shared.b64 _, [%0], %1;"
                 :: "r"(mbar), "r"(bytes) : "memory");
}
__device__ __forceinline__ unsigned sw128(unsigned byo) {
    return byo ^ ((byo >> 3) & 0x70);
}
__device__ __forceinline__ unsigned bf2u(__nv_bfloat162 h) {
    return *(unsigned*)&h;
}

// ---------------- K1: 1024 threads, 1 sentence/warp, chunked rep bulk ------
#define KBAG_SMEM (BAG_ * H_ * 4)   // 131072 (dynamic)

__global__ void __launch_bounds__(1024) k_bag(
    const float* __restrict__ rep, const float* __restrict__ aug,
    const float* __restrict__ rel_table, const int* __restrict__ labels,
    const float* __restrict__ tptr)
{
    extern __shared__ __align__(16) float srep[];        // [32][1024]
    __shared__ float4 sp[3][256];
    __shared__ float s_scores[BAG_];
    __shared__ float s_alpha[BAG_];
    __shared__ float s_red[8];
    __shared__ __align__(8) unsigned long long s_mb[8];

    int b = blockIdx.x;
    int tid = threadIdx.x, wid = tid >> 5, lane = tid & 31;
    const float* repb = rep + (size_t)b * BAG_ * H_;
    const float4* rel4 = (const float4*)(rel_table + (size_t)labels[b] * H_);
    float invT = 1.0f / tptr[0];
    unsigned smem_u = (unsigned)__cvta_generic_to_shared(srep);
    unsigned mbu    = (unsigned)__cvta_generic_to_shared(s_mb);

    // zero neg slots for this sample (wid 0..31 covers each slot twice, benign)
    g_negp[wid & (NSLOT - 1)][b * BAG_ + lane] = 0.0f;
    if (b == 0 && tid == 0) g_lsum = 0.0f;

    if (tid < 8) MBAR_INIT(mbu + 8u * tid, 1);
    __syncthreads();
    if (tid == 0) {
        #pragma unroll
        for (int c = 0; c < 8; ++c) {
            mbar_expect(mbu + 8u * c, 16384u);
            bulk_cp(smem_u + c * 16384u, repb + c * 4096, 16384u, mbu + 8u * c);
        }
    }

    const float4* srep4 = (const float4*)srep;

    // warp wid handles sentence j = wid
    {
        int j = wid;
        int n = b * BAG_ + j;
        const float4* a4 = (const float4*)(aug + (size_t)n * H_);
        char* dstb = (char*)g_rep_bf + (size_t)(n >> 3) * 1024;
        unsigned inoff = sw128((unsigned)(n & 7) * 128u + (unsigned)(lane & 15) * 8u);

        MBAR_WAIT(mbu + 8u * (j >> 2), 0);   // wait only this sentence's chunk

        float ds = 0.f, dr = 0.f, da = 0.f, dra = 0.f;
        #pragma unroll
        for (int i = 0; i < 8; ++i) {
            int t = lane + 32 * i;
            float4 rv = srep4[j * 256 + t];
            float4 av = a4[t];
            float4 rl = rel4[t];
            uint2 pk;
            pk.x = bf2u(__floats2bfloat162_rn(rv.x, rv.y));
            pk.y = bf2u(__floats2bfloat162_rn(rv.z, rv.w));
            unsigned kc = (unsigned)(lane >> 4) + 2u * i;
            *(uint2*)(dstb + (size_t)kc * (N_ * 128) + inoff) = pk;
            ds  = fmaf(rl.x, rv.x, fmaf(rl.y, rv.y, fmaf(rl.z, rv.z, fmaf(rl.w, rv.w, ds))));
            dr  = fmaf(rv.x, rv.x, fmaf(rv.y, rv.y, fmaf(rv.z, rv.z, fmaf(rv.w, rv.w, dr))));
            da  = fmaf(av.x, av.x, fmaf(av.y, av.y, fmaf(av.z, av.z, fmaf(av.w, av.w, da))));
            dra = fmaf(rv.x, av.x, fmaf(rv.y, av.y, fmaf(rv.z, av.z, fmaf(rv.w, av.w, dra))));
        }
        ds = warp_sum(ds); dr = warp_sum(dr); da = warp_sum(da); dra = warp_sum(dra);
        if (lane == 0) {
            s_scores[j] = ds * (1.0f / 32.0f);          // / sqrt(H)
            float nr = sqrtf(dr), na = sqrtf(da);
            g_rnr[n] = 1.0f / nr;
            float psim = dra / fmaxf(nr * na, EPS_);
            g_pos[n] = expf(psim * invT);
        }
    }
    __syncthreads();

    if (tid < 32) {
        float v = s_scores[tid];
        float m = warp_max(v);
        float e = expf(v - m);
        float s = warp_sum(e);
        s = __shfl_sync(0xffffffffu, s, 0);
        s_alpha[tid] = e / s;
    }
    __syncthreads();

    // pooling: quarter q sums 8 sentences for column col
    int q = tid >> 8, col = tid & 255;
    float4 acc = make_float4(0.f, 0.f, 0.f, 0.f);
    #pragma unroll
    for (int j2 = 0; j2 < 8; ++j2) {
        int j = q * 8 + j2;
        float a = s_alpha[j];
        float4 v = srep4[j * 256 + col];
        acc.x = fmaf(a, v.x, acc.x); acc.y = fmaf(a, v.y, acc.y);
        acc.z = fmaf(a, v.z, acc.z); acc.w = fmaf(a, v.w, acc.w);
    }
    if (q) sp[q - 1][col] = acc;
    __syncthreads();
    if (q == 0) {
        #pragma unroll
        for (int r = 0; r < 3; ++r) {
            float4 v = sp[r][col];
            acc.x += v.x; acc.y += v.y; acc.z += v.z; acc.w += v.w;
        }
        ((float4*)g_bag)[(size_t)b * 256 + col] = acc;
        uint2 pk;
        pk.x = bf2u(__floats2bfloat162_rn(acc.x, acc.y));
        pk.y = bf2u(__floats2bfloat162_rn(acc.z, acc.w));
        unsigned kc = (unsigned)col >> 4;
        unsigned sw = sw128((unsigned)(b & 7) * 128u + (unsigned)(col & 15) * 8u);
        *(uint2*)((char*)g_bag_bf + (size_t)kc * (B_ * 128) + (size_t)(b >> 3) * 1024 + sw) = pk;
        float nb_part = fmaf(acc.x, acc.x, fmaf(acc.y, acc.y, fmaf(acc.z, acc.z, acc.w * acc.w)));
        nb_part = warp_sum(nb_part);
        if (lane == 0) s_red[wid] = nb_part;
    }
    __syncthreads();
    if (tid == 0) {
        float s = 0.f;
        #pragma unroll
        for (int w = 0; w < 8; ++w) s += s_red[w];
        g_rnb[b] = 1.0f / sqrtf(s);
    }
}

// ---------------- K2: classifier, 64 blocks x 8 bag rows -------------------
__global__ void __launch_bounds__(256) k_clsout(
    const float* __restrict__ cls_w, const float* __restrict__ cls_b,
    float* __restrict__ out)
{
    __shared__ float4 sbag[8][256];
    int tid = threadIdx.x, wid = tid >> 5, lane = tid & 31;
    int b0 = blockIdx.x * 8;
    for (int idx = tid; idx < 2048; idx += 256)
        sbag[idx >> 8][idx & 255] =
            ((const float4*)g_bag)[(size_t)(b0 + (idx >> 8)) * 256 + (idx & 255)];
    __syncthreads();

    for (int c0 = wid * 2; c0 < C_; c0 += 16) {
        int c1 = c0 + 1;
        bool has1 = c1 < C_;
        const float4* w0 = (const float4*)(cls_w + (size_t)c0 * H_);
        const float4* w1 = (const float4*)(cls_w + (size_t)(has1 ? c1 : c0) * H_);
        float acc0[8] = {}, acc1[8] = {};
        for (int i = lane; i < 256; i += 32) {
            float4 wa = w0[i], wb = w1[i];
            #pragma unroll
            for (int r = 0; r < 8; ++r) {
                float4 v = sbag[r][i];
                acc0[r] = fmaf(wa.x, v.x, fmaf(wa.y, v.y, fmaf(wa.z, v.z, fmaf(wa.w, v.w, acc0[r]))));
                acc1[r] = fmaf(wb.x, v.x, fmaf(wb.y, v.y, fmaf(wb.z, v.z, fmaf(wb.w, v.w, acc1[r]))));
            }
        }
        #pragma unroll
        for (int r = 0; r < 8; ++r) {
            float s0 = warp_sum(acc0[r]);
            float s1 = warp_sum(acc1[r]);
            if (lane == 0) {
                out[(b0 + r) * C_ + c0] = s0 + cls_b[c0];
                if (has1) out[(b0 + r) * C_ + c1] = s1 + cls_b[c1];
            }
        }
    }
}

// ---------------- K3: bf16 HMMA pair GEMM + FMA-exp epilogue ---------------
#define STAGES 3
#define STAGE_BYTES 32768
#define NKC 16
#define PAIR_SMEM (STAGES * STAGE_BYTES)   // 98304

__global__ void __launch_bounds__(256, 2) k_pair_hmma(const float* __restrict__ tptr)
{
    extern __shared__ __align__(16) char smem[];
    __shared__ __align__(8) unsigned long long mbars[2 * STAGES];
    unsigned smem_u = (unsigned)__cvta_generic_to_shared(smem);
    unsigned mbar_u = (unsigned)__cvta_generic_to_shared(mbars);
    int tid = threadIdx.x, wid = tid >> 5, lane = tid & 31;
    int wm = wid >> 2, wn = wid & 3;
    int m0 = blockIdx.y * 128, n0 = blockIdx.x * 128;

    if (tid == 0) {
        #pragma unroll
        for (int s = 0; s < STAGES; ++s) {
            MBAR_INIT(mbar_u + 8 * s, 1);
            MBAR_INIT(mbar_u + 8 * (STAGES + s), 8);
        }
    }
    __syncthreads();

    const char* Asrc = (const char*)g_bag_bf;
    const char* Bsrc = (const char*)g_rep_bf;
    if (tid == 0) {
        #pragma unroll
        for (int s = 0; s < STAGES; ++s) {
            unsigned mb = mbar_u + 8 * s;
            mbar_expect(mb, 2 * 16384u);
            unsigned d = smem_u + s * STAGE_BYTES;
            bulk_cp(d,          Asrc + ((size_t)s * B_ + m0) * 128, 16384u, mb);
            bulk_cp(d + 16384u, Bsrc + ((size_t)s * N_ + n0) * 128, 16384u, mb);
        }
    }

    unsigned xr   = (unsigned)(lane & 7) * 16u;
    unsigned hk16 = (unsigned)(lane >> 4) * 16u;
    unsigned kb16 = (unsigned)((lane >> 3) & 1) * 16u;
    unsigned aoffb = (unsigned)((wm * 64 + (lane & 15)) * 128);
    unsigned boffb = (unsigned)((wn * 32 + ((lane >> 4) & 1) * 8 + (lane & 7)) * 128) + 16384u;

    float acc[4][4][4] = {};

    #pragma unroll 1
    for (int kc = 0; kc < NKC; ++kc) {
        int st = kc % 3;
        unsigned u = (unsigned)(kc / 3);
        MBAR_WAIT(mbar_u + 8 * st, u & 1);
        unsigned base = smem_u + st * STAGE_BYTES;
        #pragma unroll
        for (int ks = 0; ks < 4; ++ks) {
            unsigned afr[4][4], bfr[2][4];
            unsigned ksa = ((unsigned)(ks * 32) + hk16) ^ xr;
            unsigned ksb = ((unsigned)(ks * 32) + kb16) ^ xr;
            #pragma unroll
            for (int mt = 0; mt < 4; ++mt)
                LDSM4(afr[mt], base + aoffb + mt * 2048u + ksa);
            #pragma unroll
            for (int np = 0; np < 2; ++np)
                LDSM4(bfr[np], base + boffb + np * 2048u + ksb);
            #pragma unroll
            for (int mt = 0; mt < 4; ++mt)
                #pragma unroll
                for (int nt = 0; nt < 4; ++nt)
                    MMA_BF16(acc[mt][nt], afr[mt],
                             bfr[nt >> 1][(nt & 1) * 2], bfr[nt >> 1][(nt & 1) * 2 + 1]);
        }
        if (lane == 0) MBAR_ARRIVE(mbar_u + 8 * (STAGES + st));
        if (tid == 0 && kc + STAGES < NKC) {
            MBAR_WAIT(mbar_u + 8 * (STAGES + st), u & 1);
            unsigned mb = mbar_u + 8 * st;
            mbar_expect(mb, 2 * 16384u);
            unsigned d = smem_u + st * STAGE_BYTES;
            bulk_cp(d,          Asrc + ((size_t)(kc + STAGES) * B_ + m0) * 128, 16384u, mb);
            bulk_cp(d + 16384u, Bsrc + ((size_t)(kc + STAGES) * N_ + n0) * 128, 16384u, mb);
        }
    }
    __syncthreads();

    // ---- epilogue: FMA-pipe exp, single-pass smem reduce, slotted atomics ----
    float* sbuf  = (float*)smem;                    // [4][128][33]
    float* s_rnr = (float*)(smem + 67584);
    float* s_rnb = (float*)(smem + 67584 + 512);
    if (tid < 128) { s_rnr[tid] = g_rnr[n0 + tid]; s_rnb[tid] = g_rnb[m0 + tid]; }
    __syncthreads();
    float invT = 1.0f / tptr[0];
    int bglob = (n0 >> 5) + wn;
    int r0base = wm * 64 + (lane >> 2);
    float* negslot = g_negp[blockIdx.x & (NSLOT - 1)];
    float* wbuf = sbuf + wn * (128 * 33);

    #pragma unroll
    for (int mt = 0; mt < 4; ++mt) {
        int r0 = r0base + mt * 16, r1 = r0 + 8;
        float f0 = s_rnb[r0] * invT, f1 = s_rnb[r1] * invT;
        bool sk0 = (m0 + r0) == bglob, sk1 = (m0 + r1) == bglob;
        #pragma unroll
        for (int nt = 0; nt < 4; ++nt) {
            int jj = nt * 8 + (lane & 3) * 2;
            float rn0 = s_rnr[wn * 32 + jj], rn1 = s_rnr[wn * 32 + jj + 1];
            float e00 = sk0 ? 0.f : fexp(acc[mt][nt][0] * f0 * rn0);
            float e01 = sk0 ? 0.f : fexp(acc[mt][nt][1] * f0 * rn1);
            float e10 = sk1 ? 0.f : fexp(acc[mt][nt][2] * f1 * rn0);
            float e11 = sk1 ? 0.f : fexp(acc[mt][nt][3] * f1 * rn1);
            wbuf[r0 * 33 + jj]     = e00;
            wbuf[r0 * 33 + jj + 1] = e01;
            wbuf[r1 * 33 + jj]     = e10;
            wbuf[r1 * 33 + jj + 1] = e11;
        }
    }
    __syncthreads();
    for (int e = tid; e < 4096; e += 256) {
        int lc = e >> 5, jj = e & 31;
        float v = sbuf[lc * 33 + jj]
                + sbuf[1 * (128 * 33) + lc * 33 + jj]
                + sbuf[2 * (128 * 33) + lc * 33 + jj]
                + sbuf[3 * (128 * 33) + lc * 33 + jj];
        atomicAdd(&negslot[(m0 + lc) * BAG_ + jj], v);
    }
}

// ---------------- K4: loss (grid-parallel, last block finalizes) -----------
__global__ void __launch_bounds__(256) k_loss(const float* __restrict__ pos,
                                              float* __restrict__ out, int loss_idx) {
    int i = blockIdx.x * 256 + threadIdx.x;
    float t = 0.f;
    #pragma unroll
    for (int s = 0; s < NSLOT; ++s) t += g_negp[s][i];
    float v = __logf(1.0f + __fdividef(t, pos[i]));
    v = warp_sum(v);
    __shared__ float sr[8];
    if ((threadIdx.x & 31) == 0) sr[threadIdx.x >> 5] = v;
    __syncthreads();
    if (threadIdx.x == 0) {
        float s = 0.f;
        #pragma unroll
        for (int w = 0; w < 8; ++w) s += sr[w];
        atomicAdd(&g_lsum, s);
        __threadfence();
        if (atomicAdd(&g_cnt, 1) == (N_ / 256) - 1) {
            out[loss_idx] = g_lsum * (1.0f / (float)N_);
            g_cnt = 0;
        }
    }
}

// ---------------- launch ----------------
extern "C" void kernel_launch(void* const* d_in, const int* in_sizes, int n_in,
                              void* d_out, int out_size) {
    const float* rep    = (const float*)d_in[0];
    const float* aug    = (const float*)d_in[1];
    const float* rel    = (const float*)d_in[2];
    const float* cls_w  = (const float*)d_in[3];
    const float* cls_b  = (const float*)d_in[4];
    const int*   labels = (const int*)d_in[5];
    const float* temp   = (const float*)d_in[6];
    float* out = (float*)d_out;

    static cudaStream_t s2 = nullptr;
    static cudaEvent_t evA = nullptr, evB = nullptr;
    if (!s2) {
        cudaFuncSetAttribute(k_pair_hmma, cudaFuncAttributeMaxDynamicSharedMemorySize, PAIR_SMEM);
        cudaFuncSetAttribute(k_bag, cudaFuncAttributeMaxDynamicSharedMemorySize, KBAG_SMEM);
        cudaStreamCreateWithFlags(&s2, cudaStreamNonBlocking);
        cudaEventCreateWithFlags(&evA, cudaEventDisableTiming);
        cudaEventCreateWithFlags(&evB, cudaEventDisableTiming);
    }

    k_bag<<<B_, 1024, KBAG_SMEM>>>(rep, aug, rel, labels, temp);

    // fork: classifier runs on s2, overlapping the pair GEMM on the main stream
    cudaEventRecord(evA, 0);
    cudaStreamWaitEvent(s2, evA, 0);
    k_clsout<<<B_ / 8, 256, 0, s2>>>(cls_w, cls_b, out);
    cudaEventRecord(evB, s2);

    dim3 g3(N_ / 128, B_ / 128);   // (128, 4)
    k_pair_hmma<<<g3, 256, PAIR_SMEM>>>(temp);

    float* g_pos_ptr = nullptr;
    cudaGetSymbolAddress((void**)&g_pos_ptr, g_pos);
    k_loss<<<N_ / 256, 256>>>(g_pos_ptr, out, out_size - 1);

    // join
    cudaStreamWaitEvent(0, evB, 0);
}

// round 7
// speedup vs baseline: 6.4188x; 1.0179x over previous
#include <cuda_runtime.h>
#include <cuda_bf16.h>

#define B_    512
#define BAG_  32
#define H_    1024
#define C_    53
#define N_    (B_*BAG_)   // 16384
#define EPS_  1e-8f
#define NSLOT 16

// ---------------- device scratch ----------------
__device__ __align__(128) __nv_bfloat16 g_rep_bf[N_*H_];
__device__ __align__(128) __nv_bfloat16 g_bag_bf[B_*H_];
__device__ float g_bag[B_*H_];
__device__ float g_rnb[B_];
__device__ float g_rnr[N_];
__device__ float g_pos[N_];
__device__ float g_negp[NSLOT][N_];
__device__ float g_lsum;
__device__ int   g_cnt = 0;

__device__ __forceinline__ float warp_sum(float v) {
    #pragma unroll
    for (int o = 16; o; o >>= 1) v += __shfl_down_sync(0xffffffffu, v, o);
    return v;
}
__device__ __forceinline__ float warp_max(float v) {
    #pragma unroll
    for (int o = 16; o; o >>= 1) v = fmaxf(v, __shfl_xor_sync(0xffffffffu, v, o));
    return v;
}

// fast exp on the FMA pipe: no MUFU, no CVT. |x| <= 20, rel err < 3e-6.
__device__ __forceinline__ float fexp(float x) {
    const float LOG2E = 1.4426950408889634f;
    float z = fmaf(x, LOG2E, 12582912.0f);
    int   iz = __float_as_int(z);
    float r  = z - 12582912.0f;
    float f  = fmaf(x, LOG2E, -r);
    float p =            1.3298820e-3f;
    p = fmaf(p, f, 9.6179670e-3f);
    p = fmaf(p, f, 5.5503645e-2f);
    p = fmaf(p, f, 2.4022645e-1f);
    p = fmaf(p, f, 6.9314718e-1f);
    p = fmaf(p, f, 1.0f);
    unsigned sc = ((unsigned)iz + (127u - 0x4B400000u)) << 23;
    return p * __int_as_float(sc);
}

// ---------------- PTX helpers ----------
#define MBAR_INIT(addr, cnt) \
    asm volatile("mbarrier.init.shared.b64 [%0], %1;" :: "r"(addr), "r"(cnt) : "memory")

#define MBAR_WAIT(addr, par) do {                                              \
    unsigned _m = (addr), _p = (par), _d;                                      \
    asm volatile("{\n\t.reg .pred p;\n\t"                                      \
        "mbarrier.try_wait.parity.acquire.cta.shared::cta.b64 p, [%1], %2;\n\t"\
        "selp.b32 %0,1,0,p;\n\t}" : "=r"(_d) : "r"(_m), "r"(_p) : "memory");   \
    if (!_d) {                                                                 \
        asm volatile("{\n\t.reg .pred P1;\n\t"                                 \
        "WL_%=:\n\t"                                                           \
        "mbarrier.try_wait.parity.acquire.cta.shared::cta.b64 P1, [%0], %1, 0x989680;\n\t" \
        "@P1 bra.uni WD_%=;\n\t"                                               \
        "bra.uni WL_%=;\n\t"                                                   \
        "WD_%=:\n\t}" :: "r"(_m), "r"(_p) : "memory");                         \
    }                                                                          \
} while (0)

#define MBAR_ARRIVE(addr) \
    asm volatile("mbarrier.arrive.shared.b64 _, [%0];" :: "r"(addr) : "memory")

#define LDSM4(r, addr) \
    asm volatile("ldmatrix.sync.aligned.m8n8.x4.shared.b16 {%0,%1,%2,%3}, [%4];" \
        : "=r"((r)[0]), "=r"((r)[1]), "=r"((r)[2]), "=r"((r)[3]) : "r"(addr))

#define MMA_BF16(c, a, b0v, b1v) \
    asm volatile("mma.sync.aligned.m16n8k16.row.col.f32.bf16.bf16.f32 " \
        "{%0,%1,%2,%3}, {%4,%5,%6,%7}, {%8,%9}, {%0,%1,%2,%3};" \
        : "+f"((c)[0]), "+f"((c)[1]), "+f"((c)[2]), "+f"((c)[3]) \
        : "r"((a)[0]), "r"((a)[1]), "r"((a)[2]), "r"((a)[3]), "r"(b0v), "r"(b1v))

__device__ __forceinline__ void bulk_cp(unsigned dst, const void* src,
                                        unsigned bytes, unsigned mbar) {
    asm volatile(
        "cp.async.bulk.shared::cta.global.mbarrier::complete_tx::bytes [%0], [%1], %2, [%3];"
        :: "r"(dst), "l"(src), "r"(bytes), "r"(mbar) : "memory");
}
__device__ __forceinline__ void mbar_expect(unsigned mbar, unsigned bytes) {
    asm volatile("mbarrier.arrive.expect_tx.shared.b64 _, [%0], %1;"
                 :: "r"(mbar), "r"(bytes) : "memory");
}
__device__ __forceinline__ unsigned sw128(unsigned byo) {
    return byo ^ ((byo >> 3) & 0x70);
}
__device__ __forceinline__ unsigned bf2u(__nv_bfloat162 h) {
    return *(unsigned*)&h;
}

// ---------------- K1: rep-only bag pooling (critical path) -----------------
#define KBAG_SMEM (BAG_ * H_ * 4)   // 131072 (dynamic)

__global__ void __launch_bounds__(1024) k_bag(
    const float* __restrict__ rep,
    const float* __restrict__ rel_table, const int* __restrict__ labels)
{
    extern __shared__ __align__(16) float srep[];        // [32][1024]
    __shared__ float4 sp[3][256];
    __shared__ float s_scores[BAG_];
    __shared__ float s_alpha[BAG_];
    __shared__ float s_red[8];
    __shared__ __align__(8) unsigned long long s_mb[8];

    int b = blockIdx.x;
    int tid = threadIdx.x, wid = tid >> 5, lane = tid & 31;
    const float* repb = rep + (size_t)b * BAG_ * H_;
    const float4* rel4 = (const float4*)(rel_table + (size_t)labels[b] * H_);
    unsigned smem_u = (unsigned)__cvta_generic_to_shared(srep);
    unsigned mbu    = (unsigned)__cvta_generic_to_shared(s_mb);

    // zero neg slots for this sample; reset loss scalar
    g_negp[wid & (NSLOT - 1)][b * BAG_ + lane] = 0.0f;
    if (b == 0 && tid == 0) g_lsum = 0.0f;

    if (tid < 8) MBAR_INIT(mbu + 8u * tid, 1);
    __syncthreads();
    if (tid == 0) {
        #pragma unroll
        for (int c = 0; c < 8; ++c) {
            mbar_expect(mbu + 8u * c, 16384u);
            bulk_cp(smem_u + c * 16384u, repb + c * 4096, 16384u, mbu + 8u * c);
        }
    }

    const float4* srep4 = (const float4*)srep;

    // warp wid handles sentence j = wid: scores, rep norm, bf16 staging
    {
        int j = wid;
        int n = b * BAG_ + j;
        char* dstb = (char*)g_rep_bf + (size_t)(n >> 3) * 1024;
        unsigned inoff = sw128((unsigned)(n & 7) * 128u + (unsigned)(lane & 15) * 8u);

        MBAR_WAIT(mbu + 8u * (j >> 2), 0);   // wait only this sentence's chunk

        float ds = 0.f, dr = 0.f;
        #pragma unroll
        for (int i = 0; i < 8; ++i) {
            int t = lane + 32 * i;
            float4 rv = srep4[j * 256 + t];
            float4 rl = rel4[t];
            uint2 pk;
            pk.x = bf2u(__floats2bfloat162_rn(rv.x, rv.y));
            pk.y = bf2u(__floats2bfloat162_rn(rv.z, rv.w));
            unsigned kc = (unsigned)(lane >> 4) + 2u * i;
            *(uint2*)(dstb + (size_t)kc * (N_ * 128) + inoff) = pk;
            ds = fmaf(rl.x, rv.x, fmaf(rl.y, rv.y, fmaf(rl.z, rv.z, fmaf(rl.w, rv.w, ds))));
            dr = fmaf(rv.x, rv.x, fmaf(rv.y, rv.y, fmaf(rv.z, rv.z, fmaf(rv.w, rv.w, dr))));
        }
        ds = warp_sum(ds); dr = warp_sum(dr);
        if (lane == 0) {
            s_scores[j] = ds * (1.0f / 32.0f);          // / sqrt(H)
            g_rnr[n] = 1.0f / sqrtf(dr);
        }
    }
    __syncthreads();

    if (tid < 32) {
        float v = s_scores[tid];
        float m = warp_max(v);
        float e = expf(v - m);
        float s = warp_sum(e);
        s = __shfl_sync(0xffffffffu, s, 0);
        s_alpha[tid] = e / s;
    }
    __syncthreads();

    // pooling: quarter q sums 8 sentences for column col
    int q = tid >> 8, col = tid & 255;
    float4 acc = make_float4(0.f, 0.f, 0.f, 0.f);
    #pragma unroll
    for (int j2 = 0; j2 < 8; ++j2) {
        int j = q * 8 + j2;
        float a = s_alpha[j];
        float4 v = srep4[j * 256 + col];
        acc.x = fmaf(a, v.x, acc.x); acc.y = fmaf(a, v.y, acc.y);
        acc.z = fmaf(a, v.z, acc.z); acc.w = fmaf(a, v.w, acc.w);
    }
    if (q) sp[q - 1][col] = acc;
    __syncthreads();
    if (q == 0) {
        #pragma unroll
        for (int r = 0; r < 3; ++r) {
            float4 v = sp[r][col];
            acc.x += v.x; acc.y += v.y; acc.z += v.z; acc.w += v.w;
        }
        ((float4*)g_bag)[(size_t)b * 256 + col] = acc;
        uint2 pk;
        pk.x = bf2u(__floats2bfloat162_rn(acc.x, acc.y));
        pk.y = bf2u(__floats2bfloat162_rn(acc.z, acc.w));
        unsigned kc = (unsigned)col >> 4;
        unsigned sw = sw128((unsigned)(b & 7) * 128u + (unsigned)(col & 15) * 8u);
        *(uint2*)((char*)g_bag_bf + (size_t)kc * (B_ * 128) + (size_t)(b >> 3) * 1024 + sw) = pk;
        float nb_part = fmaf(acc.x, acc.x, fmaf(acc.y, acc.y, fmaf(acc.z, acc.z, acc.w * acc.w)));
        nb_part = warp_sum(nb_part);
        if (lane == 0) s_red[wid] = nb_part;
    }
    __syncthreads();
    if (tid == 0) {
        float s = 0.f;
        #pragma unroll
        for (int w = 0; w < 8; ++w) s += s_red[w];
        g_rnb[b] = 1.0f / sqrtf(s);
    }
}

// ---------------- K1b: pos term (off critical path, overlaps k_pair) -------
__global__ void __launch_bounds__(256) k_pos(
    const float* __restrict__ rep, const float* __restrict__ aug,
    const float* __restrict__ tptr)
{
    int b = blockIdx.x;
    int tid = threadIdx.x, wid = tid >> 5, lane = tid & 31;
    float invT = 1.0f / tptr[0];

    for (int j = wid; j < BAG_; j += 8) {
        int n = b * BAG_ + j;
        const float4* r4 = (const float4*)(rep + (size_t)n * H_);
        const float4* a4 = (const float4*)(aug + (size_t)n * H_);
        float da = 0.f, dra = 0.f;
        #pragma unroll
        for (int i = 0; i < 8; ++i) {
            int t = lane + 32 * i;
            float4 rv = r4[t], av = a4[t];
            da  = fmaf(av.x, av.x, fmaf(av.y, av.y, fmaf(av.z, av.z, fmaf(av.w, av.w, da))));
            dra = fmaf(rv.x, av.x, fmaf(rv.y, av.y, fmaf(rv.z, av.z, fmaf(rv.w, av.w, dra))));
        }
        da = warp_sum(da); dra = warp_sum(dra);
        if (lane == 0) {
            float na = sqrtf(da);
            float nr = 1.0f / g_rnr[n];
            float psim = dra / fmaxf(nr * na, EPS_);
            g_pos[n] = expf(psim * invT);
        }
    }
}

// ---------------- K2: classifier, 64 blocks x 8 bag rows -------------------
__global__ void __launch_bounds__(256) k_clsout(
    const float* __restrict__ cls_w, const float* __restrict__ cls_b,
    float* __restrict__ out)
{
    __shared__ float4 sbag[8][256];
    int tid = threadIdx.x, wid = tid >> 5, lane = tid & 31;
    int b0 = blockIdx.x * 8;
    for (int idx = tid; idx < 2048; idx += 256)
        sbag[idx >> 8][idx & 255] =
            ((const float4*)g_bag)[(size_t)(b0 + (idx >> 8)) * 256 + (idx & 255)];
    __syncthreads();

    for (int c0 = wid * 2; c0 < C_; c0 += 16) {
        int c1 = c0 + 1;
        bool has1 = c1 < C_;
        const float4* w0 = (const float4*)(cls_w + (size_t)c0 * H_);
        const float4* w1 = (const float4*)(cls_w + (size_t)(has1 ? c1 : c0) * H_);
        float acc0[8] = {}, acc1[8] = {};
        for (int i = lane; i < 256; i += 32) {
            float4 wa = w0[i], wb = w1[i];
            #pragma unroll
            for (int r = 0; r < 8; ++r) {
                float4 v = sbag[r][i];
                acc0[r] = fmaf(wa.x, v.x, fmaf(wa.y, v.y, fmaf(wa.z, v.z, fmaf(wa.w, v.w, acc0[r]))));
                acc1[r] = fmaf(wb.x, v.x, fmaf(wb.y, v.y, fmaf(wb.z, v.z, fmaf(wb.w, v.w, acc1[r]))));
            }
        }
        #pragma unroll
        for (int r = 0; r < 8; ++r) {
            float s0 = warp_sum(acc0[r]);
            float s1 = warp_sum(acc1[r]);
            if (lane == 0) {
                out[(b0 + r) * C_ + c0] = s0 + cls_b[c0];
                if (has1) out[(b0 + r) * C_ + c1] = s1 + cls_b[c1];
            }
        }
    }
}

// ---------------- K3: bf16 HMMA pair GEMM + FMA-exp epilogue ---------------
#define STAGES 3
#define STAGE_BYTES 32768
#define NKC 16
#define PAIR_SMEM (STAGES * STAGE_BYTES)   // 98304

__global__ void __launch_bounds__(256, 2) k_pair_hmma(const float* __restrict__ tptr)
{
    extern __shared__ __align__(16) char smem[];
    __shared__ __align__(8) unsigned long long mbars[2 * STAGES];
    unsigned smem_u = (unsigned)__cvta_generic_to_shared(smem);
    unsigned mbar_u = (unsigned)__cvta_generic_to_shared(mbars);
    int tid = threadIdx.x, wid = tid >> 5, lane = tid & 31;
    int wm = wid >> 2, wn = wid & 3;
    int m0 = blockIdx.y * 128, n0 = blockIdx.x * 128;

    if (tid == 0) {
        #pragma unroll
        for (int s = 0; s < STAGES; ++s) {
            MBAR_INIT(mbar_u + 8 * s, 1);
            MBAR_INIT(mbar_u + 8 * (STAGES + s), 8);
        }
    }
    __syncthreads();

    const char* Asrc = (const char*)g_bag_bf;
    const char* Bsrc = (const char*)g_rep_bf;
    if (tid == 0) {
        #pragma unroll
        for (int s = 0; s < STAGES; ++s) {
            unsigned mb = mbar_u + 8 * s;
            mbar_expect(mb, 2 * 16384u);
            unsigned d = smem_u + s * STAGE_BYTES;
            bulk_cp(d,          Asrc + ((size_t)s * B_ + m0) * 128, 16384u, mb);
            bulk_cp(d + 16384u, Bsrc + ((size_t)s * N_ + n0) * 128, 16384u, mb);
        }
    }

    unsigned xr   = (unsigned)(lane & 7) * 16u;
    unsigned hk16 = (unsigned)(lane >> 4) * 16u;
    unsigned kb16 = (unsigned)((lane >> 3) & 1) * 16u;
    unsigned aoffb = (unsigned)((wm * 64 + (lane & 15)) * 128);
    unsigned boffb = (unsigned)((wn * 32 + ((lane >> 4) & 1) * 8 + (lane & 7)) * 128) + 16384u;

    float acc[4][4][4] = {};

    #pragma unroll 1
    for (int kc = 0; kc < NKC; ++kc) {
        int st = kc % 3;
        unsigned u = (unsigned)(kc / 3);
        MBAR_WAIT(mbar_u + 8 * st, u & 1);
        unsigned base = smem_u + st * STAGE_BYTES;
        #pragma unroll
        for (int ks = 0; ks < 4; ++ks) {
            unsigned afr[4][4], bfr[2][4];
            unsigned ksa = ((unsigned)(ks * 32) + hk16) ^ xr;
            unsigned ksb = ((unsigned)(ks * 32) + kb16) ^ xr;
            #pragma unroll
            for (int mt = 0; mt < 4; ++mt)
                LDSM4(afr[mt], base + aoffb + mt * 2048u + ksa);
            #pragma unroll
            for (int np = 0; np < 2; ++np)
                LDSM4(bfr[np], base + boffb + np * 2048u + ksb);
            #pragma unroll
            for (int mt = 0; mt < 4; ++mt)
                #pragma unroll
                for (int nt = 0; nt < 4; ++nt)
                    MMA_BF16(acc[mt][nt], afr[mt],
                             bfr[nt >> 1][(nt & 1) * 2], bfr[nt >> 1][(nt & 1) * 2 + 1]);
        }
        if (lane == 0) MBAR_ARRIVE(mbar_u + 8 * (STAGES + st));
        if (tid == 0 && kc + STAGES < NKC) {
            MBAR_WAIT(mbar_u + 8 * (STAGES + st), u & 1);
            unsigned mb = mbar_u + 8 * st;
            mbar_expect(mb, 2 * 16384u);
            unsigned d = smem_u + st * STAGE_BYTES;
            bulk_cp(d,          Asrc + ((size_t)(kc + STAGES) * B_ + m0) * 128, 16384u, mb);
            bulk_cp(d + 16384u, Bsrc + ((size_t)(kc + STAGES) * N_ + n0) * 128, 16384u, mb);
        }
    }
    __syncthreads();

    // ---- epilogue: FMA-pipe exp, single-pass smem reduce, slotted atomics ----
    float* sbuf  = (float*)smem;                    // [4][128][33]
    float* s_rnr = (float*)(smem + 67584);
    float* s_rnb = (float*)(smem + 67584 + 512);
    if (tid < 128) { s_rnr[tid] = g_rnr[n0 + tid]; s_rnb[tid] = g_rnb[m0 + tid]; }
    __syncthreads();
    float invT = 1.0f / tptr[0];
    int bglob = (n0 >> 5) + wn;
    int r0base = wm * 64 + (lane >> 2);
    float* negslot = g_negp[blockIdx.x & (NSLOT - 1)];
    float* wbuf = sbuf + wn * (128 * 33);

    #pragma unroll
    for (int mt = 0; mt < 4; ++mt) {
        int r0 = r0base + mt * 16, r1 = r0 + 8;
        float f0 = s_rnb[r0] * invT, f1 = s_rnb[r1] * invT;
        bool sk0 = (m0 + r0) == bglob, sk1 = (m0 + r1) == bglob;
        #pragma unroll
        for (int nt = 0; nt < 4; ++nt) {
            int jj = nt * 8 + (lane & 3) * 2;
            float rn0 = s_rnr[wn * 32 + jj], rn1 = s_rnr[wn * 32 + jj + 1];
            float e00 = sk0 ? 0.f : fexp(acc[mt][nt][0] * f0 * rn0);
            float e01 = sk0 ? 0.f : fexp(acc[mt][nt][1] * f0 * rn1);
            float e10 = sk1 ? 0.f : fexp(acc[mt][nt][2] * f1 * rn0);
            float e11 = sk1 ? 0.f : fexp(acc[mt][nt][3] * f1 * rn1);
            wbuf[r0 * 33 + jj]     = e00;
            wbuf[r0 * 33 + jj + 1] = e01;
            wbuf[r1 * 33 + jj]     = e10;
            wbuf[r1 * 33 + jj + 1] = e11;
        }
    }
    __syncthreads();
    for (int e = tid; e < 4096; e += 256) {
        int lc = e >> 5, jj = e & 31;
        float v = sbuf[lc * 33 + jj]
                + sbuf[1 * (128 * 33) + lc * 33 + jj]
                + sbuf[2 * (128 * 33) + lc * 33 + jj]
                + sbuf[3 * (128 * 33) + lc * 33 + jj];
        atomicAdd(&negslot[(m0 + lc) * BAG_ + jj], v);
    }
}

// ---------------- K4: loss (grid-parallel, last block finalizes) -----------
__global__ void __launch_bounds__(256) k_loss(const float* __restrict__ pos,
                                              float* __restrict__ out, int loss_idx) {
    int i = blockIdx.x * 256 + threadIdx.x;
    float t = 0.f;
    #pragma unroll
    for (int s = 0; s < NSLOT; ++s) t += g_negp[s][i];
    float v = __logf(1.0f + __fdividef(t, pos[i]));
    v = warp_sum(v);
    __shared__ float sr[8];
    if ((threadIdx.x & 31) == 0) sr[threadIdx.x >> 5] = v;
    __syncthreads();
    if (threadIdx.x == 0) {
        float s = 0.f;
        #pragma unroll
        for (int w = 0; w < 8; ++w) s += sr[w];
        atomicAdd(&g_lsum, s);
        __threadfence();
        if (atomicAdd(&g_cnt, 1) == (N_ / 256) - 1) {
            out[loss_idx] = g_lsum * (1.0f / (float)N_);
            g_cnt = 0;
        }
    }
}

// ---------------- launch ----------------
extern "C" void kernel_launch(void* const* d_in, const int* in_sizes, int n_in,
                              void* d_out, int out_size) {
    const float* rep    = (const float*)d_in[0];
    const float* aug    = (const float*)d_in[1];
    const float* rel    = (const float*)d_in[2];
    const float* cls_w  = (const float*)d_in[3];
    const float* cls_b  = (const float*)d_in[4];
    const int*   labels = (const int*)d_in[5];
    const float* temp   = (const float*)d_in[6];
    float* out = (float*)d_out;

    static cudaStream_t s2 = nullptr;
    static cudaEvent_t evA = nullptr, evB = nullptr;
    if (!s2) {
        cudaFuncSetAttribute(k_pair_hmma, cudaFuncAttributeMaxDynamicSharedMemorySize, PAIR_SMEM);
        cudaFuncSetAttribute(k_bag, cudaFuncAttributeMaxDynamicSharedMemorySize, KBAG_SMEM);
        cudaStreamCreateWithFlags(&s2, cudaStreamNonBlocking);
        cudaEventCreateWithFlags(&evA, cudaEventDisableTiming);
        cudaEventCreateWithFlags(&evB, cudaEventDisableTiming);
    }

    // critical path: k_bag -> k_pair -> k_loss
    k_bag<<<B_, 1024, KBAG_SMEM>>>(rep, rel, labels);

    // fork: classifier + pos run on s2, overlapping the pair GEMM
    cudaEventRecord(evA, 0);
    cudaStreamWaitEvent(s2, evA, 0);
    k_clsout<<<B_ / 8, 256, 0, s2>>>(cls_w, cls_b, out);
    k_pos<<<B_, 256, 0, s2>>>(rep, aug, temp);
    cudaEventRecord(evB, s2);

    dim3 g3(N_ / 128, B_ / 128);   // (128, 4)
    k_pair_hmma<<<g3, 256, PAIR_SMEM>>>(temp);

    // join: k_loss needs g_pos (s2) and g_negp (main)
    cudaStreamWaitEvent(0, evB, 0);
    float* g_pos_ptr = nullptr;
    cudaGetSymbolAddress((void**)&g_pos_ptr, g_pos);
    k_loss<<<N_ / 256, 256>>>(g_pos_ptr, out, out_size - 1);
}

// round 8
// speedup vs baseline: 6.9761x; 1.0868x over previous
#include <cuda_runtime.h>
#include <cuda_bf16.h>

#define B_    512
#define BAG_  32
#define H_    1024
#define C_    53
#define N_    (B_*BAG_)   // 16384
#define EPS_  1e-8f
#define NSLOT 16

// ---------------- device scratch ----------------
__device__ __align__(128) __nv_bfloat16 g_rep_bf[N_*H_];
__device__ __align__(128) __nv_bfloat16 g_bag_bf[B_*H_];
__device__ float g_bag[B_*H_];
__device__ float g_rnb[B_];
__device__ float g_rnr[N_];
__device__ float g_pos[N_];
__device__ float g_negp[NSLOT][N_];
__device__ float g_lsum;
__device__ int   g_cnt = 0;

__device__ __forceinline__ float warp_sum(float v) {
    #pragma unroll
    for (int o = 16; o; o >>= 1) v += __shfl_down_sync(0xffffffffu, v, o);
    return v;
}
__device__ __forceinline__ float warp_max(float v) {
    #pragma unroll
    for (int o = 16; o; o >>= 1) v = fmaxf(v, __shfl_xor_sync(0xffffffffu, v, o));
    return v;
}

// fast exp on the FMA pipe: no MUFU, no CVT. |x| <= 20, rel err < 3e-6.
__device__ __forceinline__ float fexp(float x) {
    const float LOG2E = 1.4426950408889634f;
    float z = fmaf(x, LOG2E, 12582912.0f);
    int   iz = __float_as_int(z);
    float r  = z - 12582912.0f;
    float f  = fmaf(x, LOG2E, -r);
    float p =            1.3298820e-3f;
    p = fmaf(p, f, 9.6179670e-3f);
    p = fmaf(p, f, 5.5503645e-2f);
    p = fmaf(p, f, 2.4022645e-1f);
    p = fmaf(p, f, 6.9314718e-1f);
    p = fmaf(p, f, 1.0f);
    unsigned sc = ((unsigned)iz + (127u - 0x4B400000u)) << 23;
    return p * __int_as_float(sc);
}

// ---------------- PTX helpers ----------
#define MBAR_INIT(addr, cnt) \
    asm volatile("mbarrier.init.shared.b64 [%0], %1;" :: "r"(addr), "r"(cnt) : "memory")

#define MBAR_WAIT(addr, par) do {                                              \
    unsigned _m = (addr), _p = (par), _d;                                      \
    asm volatile("{\n\t.reg .pred p;\n\t"                                      \
        "mbarrier.try_wait.parity.acquire.cta.shared::cta.b64 p, [%1], %2;\n\t"\
        "selp.b32 %0,1,0,p;\n\t}" : "=r"(_d) : "r"(_m), "r"(_p) : "memory");   \
    if (!_d) {                                                                 \
        asm volatile("{\n\t.reg .pred P1;\n\t"                                 \
        "WL_%=:\n\t"                                                           \
        "mbarrier.try_wait.parity.acquire.cta.shared::cta.b64 P1, [%0], %1, 0x989680;\n\t" \
        "@P1 bra.uni WD_%=;\n\t"                                               \
        "bra.uni WL_%=;\n\t"                                                   \
        "WD_%=:\n\t}" :: "r"(_m), "r"(_p) : "memory");                         \
    }                                                                          \
} while (0)

#define MBAR_ARRIVE(addr) \
    asm volatile("mbarrier.arrive.shared.b64 _, [%0];" :: "r"(addr) : "memory")

#define LDSM4(r, addr) \
    asm volatile("ldmatrix.sync.aligned.m8n8.x4.shared.b16 {%0,%1,%2,%3}, [%4];" \
        : "=r"((r)[0]), "=r"((r)[1]), "=r"((r)[2]), "=r"((r)[3]) : "r"(addr))

#define MMA_BF16(c, a, b0v, b1v) \
    asm volatile("mma.sync.aligned.m16n8k16.row.col.f32.bf16.bf16.f32 " \
        "{%0,%1,%2,%3}, {%4,%5,%6,%7}, {%8,%9}, {%0,%1,%2,%3};" \
        : "+f"((c)[0]), "+f"((c)[1]), "+f"((c)[2]), "+f"((c)[3]) \
        : "r"((a)[0]), "r"((a)[1]), "r"((a)[2]), "r"((a)[3]), "r"(b0v), "r"(b1v))

__device__ __forceinline__ void bulk_cp(unsigned dst, const void* src,
                                        unsigned bytes, unsigned mbar) {
    asm volatile(
        "cp.async.bulk.shared::cta.global.mbarrier::complete_tx::bytes [%0], [%1], %2, [%3];"
        :: "r"(dst), "l"(src), "r"(bytes), "r"(mbar) : "memory");
}
__device__ __forceinline__ void mbar_expect(unsigned mbar, unsigned bytes) {
    asm volatile("mbarrier.arrive.expect_tx.shared.b64 _, [%0], %1;"
                 :: "r"(mbar), "r"(bytes) : "memory");
}
__device__ __forceinline__ unsigned sw128(unsigned byo) {
    return byo ^ ((byo >> 3) & 0x70);
}
__device__ __forceinline__ unsigned bf2u(__nv_bfloat162 h) {
    return *(unsigned*)&h;
}

// ---------------- K1: rep-only bag pooling, no bulk staging ----------------
__global__ void __launch_bounds__(256) k_bag(
    const float* __restrict__ rep,
    const float* __restrict__ rel_table, const int* __restrict__ labels)
{
    __shared__ float s_scores[BAG_];
    __shared__ float s_alpha[BAG_];
    __shared__ float s_red[8];

    int b = blockIdx.x;
    int tid = threadIdx.x, wid = tid >> 5, lane = tid & 31;
    const float* repb = rep + (size_t)b * BAG_ * H_;
    const float4* rel4 = (const float4*)(rel_table + (size_t)labels[b] * H_);

    // zero neg slots for this sample; reset loss scalar
    #pragma unroll
    for (int q = 0; q < 2; ++q)
        g_negp[wid + q * 8][b * BAG_ + lane] = 0.0f;
    if (b == 0 && tid == 0) g_lsum = 0.0f;

    // each warp: 4 sentences — scores, rep norm, bf16 staging
    for (int j = wid; j < BAG_; j += 8) {
        const float4* r4 = (const float4*)(repb + (size_t)j * H_);
        int n = b * BAG_ + j;
        char* dstb = (char*)g_rep_bf + (size_t)(n >> 3) * 1024;
        unsigned inoff = sw128((unsigned)(n & 7) * 128u + (unsigned)(lane & 15) * 8u);
        float ds = 0.f, dr = 0.f;
        #pragma unroll
        for (int i = 0; i < 8; ++i) {
            int t = lane + 32 * i;
            float4 rv = r4[t];
            float4 rl = rel4[t];
            uint2 pk;
            pk.x = bf2u(__floats2bfloat162_rn(rv.x, rv.y));
            pk.y = bf2u(__floats2bfloat162_rn(rv.z, rv.w));
            unsigned kc = (unsigned)(lane >> 4) + 2u * i;
            *(uint2*)(dstb + (size_t)kc * (N_ * 128) + inoff) = pk;
            ds = fmaf(rl.x, rv.x, fmaf(rl.y, rv.y, fmaf(rl.z, rv.z, fmaf(rl.w, rv.w, ds))));
            dr = fmaf(rv.x, rv.x, fmaf(rv.y, rv.y, fmaf(rv.z, rv.z, fmaf(rv.w, rv.w, dr))));
        }
        ds = warp_sum(ds); dr = warp_sum(dr);
        if (lane == 0) {
            s_scores[j] = ds * (1.0f / 32.0f);          // / sqrt(H)
            g_rnr[n] = 1.0f / sqrtf(dr);
        }
    }
    __syncthreads();

    if (tid < 32) {
        float v = s_scores[tid];
        float m = warp_max(v);
        float e = expf(v - m);
        float s = warp_sum(e);
        s = __shfl_sync(0xffffffffu, s, 0);
        s_alpha[tid] = e / s;
    }
    __syncthreads();

    // pooling: one float4 column per thread, rows L1/L2-hot from phase A
    const float4* rp4 = (const float4*)repb;
    float4 acc = make_float4(0.f, 0.f, 0.f, 0.f);
    #pragma unroll 8
    for (int j = 0; j < BAG_; ++j) {
        float4 v = rp4[(size_t)j * 256 + tid];
        float a = s_alpha[j];
        acc.x = fmaf(a, v.x, acc.x); acc.y = fmaf(a, v.y, acc.y);
        acc.z = fmaf(a, v.z, acc.z); acc.w = fmaf(a, v.w, acc.w);
    }
    ((float4*)g_bag)[(size_t)b * 256 + tid] = acc;
    {
        uint2 pk;
        pk.x = bf2u(__floats2bfloat162_rn(acc.x, acc.y));
        pk.y = bf2u(__floats2bfloat162_rn(acc.z, acc.w));
        unsigned kc = (unsigned)tid >> 4;
        unsigned sw = sw128((unsigned)(b & 7) * 128u + (unsigned)(tid & 15) * 8u);
        *(uint2*)((char*)g_bag_bf + (size_t)kc * (B_ * 128) + (size_t)(b >> 3) * 1024 + sw) = pk;
    }
    float nb_part = fmaf(acc.x, acc.x, fmaf(acc.y, acc.y, fmaf(acc.z, acc.z, acc.w * acc.w)));
    nb_part = warp_sum(nb_part);
    if (lane == 0) s_red[wid] = nb_part;
    __syncthreads();
    if (tid == 0) {
        float s = 0.f;
        #pragma unroll
        for (int w = 0; w < 8; ++w) s += s_red[w];
        g_rnb[b] = 1.0f / sqrtf(s);
    }
}

// ---------------- K1b: pos term (off critical path, overlaps k_pair) -------
__global__ void __launch_bounds__(256) k_pos(
    const float* __restrict__ rep, const float* __restrict__ aug,
    const float* __restrict__ tptr)
{
    int b = blockIdx.x;
    int tid = threadIdx.x, wid = tid >> 5, lane = tid & 31;
    float invT = 1.0f / tptr[0];

    for (int j = wid; j < BAG_; j += 8) {
        int n = b * BAG_ + j;
        const float4* r4 = (const float4*)(rep + (size_t)n * H_);
        const float4* a4 = (const float4*)(aug + (size_t)n * H_);
        float da = 0.f, dra = 0.f;
        #pragma unroll
        for (int i = 0; i < 8; ++i) {
            int t = lane + 32 * i;
            float4 rv = r4[t], av = a4[t];
            da  = fmaf(av.x, av.x, fmaf(av.y, av.y, fmaf(av.z, av.z, fmaf(av.w, av.w, da))));
            dra = fmaf(rv.x, av.x, fmaf(rv.y, av.y, fmaf(rv.z, av.z, fmaf(rv.w, av.w, dra))));
        }
        da = warp_sum(da); dra = warp_sum(dra);
        if (lane == 0) {
            float na = sqrtf(da);
            float nr = 1.0f / g_rnr[n];
            float psim = dra / fmaxf(nr * na, EPS_);
            g_pos[n] = expf(psim * invT);
        }
    }
}

// ---------------- K2: classifier, 64 blocks x 8 bag rows -------------------
__global__ void __launch_bounds__(256) k_clsout(
    const float* __restrict__ cls_w, const float* __restrict__ cls_b,
    float* __restrict__ out)
{
    __shared__ float4 sbag[8][256];
    int tid = threadIdx.x, wid = tid >> 5, lane = tid & 31;
    int b0 = blockIdx.x * 8;
    for (int idx = tid; idx < 2048; idx += 256)
        sbag[idx >> 8][idx & 255] =
            ((const float4*)g_bag)[(size_t)(b0 + (idx >> 8)) * 256 + (idx & 255)];
    __syncthreads();

    for (int c0 = wid * 2; c0 < C_; c0 += 16) {
        int c1 = c0 + 1;
        bool has1 = c1 < C_;
        const float4* w0 = (const float4*)(cls_w + (size_t)c0 * H_);
        const float4* w1 = (const float4*)(cls_w + (size_t)(has1 ? c1 : c0) * H_);
        float acc0[8] = {}, acc1[8] = {};
        for (int i = lane; i < 256; i += 32) {
            float4 wa = w0[i], wb = w1[i];
            #pragma unroll
            for (int r = 0; r < 8; ++r) {
                float4 v = sbag[r][i];
                acc0[r] = fmaf(wa.x, v.x, fmaf(wa.y, v.y, fmaf(wa.z, v.z, fmaf(wa.w, v.w, acc0[r]))));
                acc1[r] = fmaf(wb.x, v.x, fmaf(wb.y, v.y, fmaf(wb.z, v.z, fmaf(wb.w, v.w, acc1[r]))));
            }
        }
        #pragma unroll
        for (int r = 0; r < 8; ++r) {
            float s0 = warp_sum(acc0[r]);
            float s1 = warp_sum(acc1[r]);
            if (lane == 0) {
                out[(b0 + r) * C_ + c0] = s0 + cls_b[c0];
                if (has1) out[(b0 + r) * C_ + c1] = s1 + cls_b[c1];
            }
        }
    }
}

// ---------------- K3: bf16 HMMA pair GEMM + FMA-exp epilogue ---------------
#define STAGES 3
#define STAGE_BYTES 32768
#define NKC 16
#define PAIR_SMEM (STAGES * STAGE_BYTES)   // 98304

__global__ void __launch_bounds__(256, 2) k_pair_hmma(const float* __restrict__ tptr)
{
    extern __shared__ __align__(16) char smem[];
    __shared__ __align__(8) unsigned long long mbars[2 * STAGES];
    unsigned smem_u = (unsigned)__cvta_generic_to_shared(smem);
    unsigned mbar_u = (unsigned)__cvta_generic_to_shared(mbars);
    int tid = threadIdx.x, wid = tid >> 5, lane = tid & 31;
    int wm = wid >> 2, wn = wid & 3;
    int m0 = blockIdx.y * 128, n0 = blockIdx.x * 128;

    if (tid == 0) {
        #pragma unroll
        for (int s = 0; s < STAGES; ++s) {
            MBAR_INIT(mbar_u + 8 * s, 1);
            MBAR_INIT(mbar_u + 8 * (STAGES + s), 8);
        }
    }
    __syncthreads();

    const char* Asrc = (const char*)g_bag_bf;
    const char* Bsrc = (const char*)g_rep_bf;
    if (tid == 0) {
        #pragma unroll
        for (int s = 0; s < STAGES; ++s) {
            unsigned mb = mbar_u + 8 * s;
            mbar_expect(mb, 2 * 16384u);
            unsigned d = smem_u + s * STAGE_BYTES;
            bulk_cp(d,          Asrc + ((size_t)s * B_ + m0) * 128, 16384u, mb);
            bulk_cp(d + 16384u, Bsrc + ((size_t)s * N_ + n0) * 128, 16384u, mb);
        }
    }

    unsigned xr   = (unsigned)(lane & 7) * 16u;
    unsigned hk16 = (unsigned)(lane >> 4) * 16u;
    unsigned kb16 = (unsigned)((lane >> 3) & 1) * 16u;
    unsigned aoffb = (unsigned)((wm * 64 + (lane & 15)) * 128);
    unsigned boffb = (unsigned)((wn * 32 + ((lane >> 4) & 1) * 8 + (lane & 7)) * 128) + 16384u;

    float acc[4][4][4] = {};

    #pragma unroll 1
    for (int kc = 0; kc < NKC; ++kc) {
        int st = kc % 3;
        unsigned u = (unsigned)(kc / 3);
        MBAR_WAIT(mbar_u + 8 * st, u & 1);
        unsigned base = smem_u + st * STAGE_BYTES;
        #pragma unroll
        for (int ks = 0; ks < 4; ++ks) {
            unsigned afr[4][4], bfr[2][4];
            unsigned ksa = ((unsigned)(ks * 32) + hk16) ^ xr;
            unsigned ksb = ((unsigned)(ks * 32) + kb16) ^ xr;
            #pragma unroll
            for (int mt = 0; mt < 4; ++mt)
                LDSM4(afr[mt], base + aoffb + mt * 2048u + ksa);
            #pragma unroll
            for (int np = 0; np < 2; ++np)
                LDSM4(bfr[np], base + boffb + np * 2048u + ksb);
            #pragma unroll
            for (int mt = 0; mt < 4; ++mt)
                #pragma unroll
                for (int nt = 0; nt < 4; ++nt)
                    MMA_BF16(acc[mt][nt], afr[mt],
                             bfr[nt >> 1][(nt & 1) * 2], bfr[nt >> 1][(nt & 1) * 2 + 1]);
        }
        if (lane == 0) MBAR_ARRIVE(mbar_u + 8 * (STAGES + st));
        // rotating producer: a different warp refills each kc
        if (kc + STAGES < NKC && wid == (kc & 7) && lane == 0) {
            MBAR_WAIT(mbar_u + 8 * (STAGES + st), u & 1);
            unsigned mb = mbar_u + 8 * st;
            mbar_expect(mb, 2 * 16384u);
            unsigned d = smem_u + st * STAGE_BYTES;
            bulk_cp(d,          Asrc + ((size_t)(kc + STAGES) * B_ + m0) * 128, 16384u, mb);
            bulk_cp(d + 16384u, Bsrc + ((size_t)(kc + STAGES) * N_ + n0) * 128, 16384u, mb);
        }
    }
    __syncthreads();

    // ---- epilogue: FMA-pipe exp, single-pass smem reduce, slotted atomics ----
    float* sbuf  = (float*)smem;                    // [4][128][33]
    float* s_rnr = (float*)(smem + 67584);
    float* s_rnb = (float*)(smem + 67584 + 512);
    if (tid < 128) { s_rnr[tid] = g_rnr[n0 + tid]; s_rnb[tid] = g_rnb[m0 + tid]; }
    __syncthreads();
    float invT = 1.0f / tptr[0];
    int bglob = (n0 >> 5) + wn;
    int r0base = wm * 64 + (lane >> 2);
    float* negslot = g_negp[blockIdx.x & (NSLOT - 1)];
    float* wbuf = sbuf + wn * (128 * 33);

    #pragma unroll
    for (int mt = 0; mt < 4; ++mt) {
        int r0 = r0base + mt * 16, r1 = r0 + 8;
        float f0 = s_rnb[r0] * invT, f1 = s_rnb[r1] * invT;
        bool sk0 = (m0 + r0) == bglob, sk1 = (m0 + r1) == bglob;
        #pragma unroll
        for (int nt = 0; nt < 4; ++nt) {
            int jj = nt * 8 + (lane & 3) * 2;
            float rn0 = s_rnr[wn * 32 + jj], rn1 = s_rnr[wn * 32 + jj + 1];
            float e00 = sk0 ? 0.f : fexp(acc[mt][nt][0] * f0 * rn0);
            float e01 = sk0 ? 0.f : fexp(acc[mt][nt][1] * f0 * rn1);
            float e10 = sk1 ? 0.f : fexp(acc[mt][nt][2] * f1 * rn0);
            float e11 = sk1 ? 0.f : fexp(acc[mt][nt][3] * f1 * rn1);
            wbuf[r0 * 33 + jj]     = e00;
            wbuf[r0 * 33 + jj + 1] = e01;
            wbuf[r1 * 33 + jj]     = e10;
            wbuf[r1 * 33 + jj + 1] = e11;
        }
    }
    __syncthreads();
    for (int e = tid; e < 4096; e += 256) {
        int lc = e >> 5, jj = e & 31;
        float v = sbuf[lc * 33 + jj]
                + sbuf[1 * (128 * 33) + lc * 33 + jj]
                + sbuf[2 * (128 * 33) + lc * 33 + jj]
                + sbuf[3 * (128 * 33) + lc * 33 + jj];
        atomicAdd(&negslot[(m0 + lc) * BAG_ + jj], v);
    }
}

// ---------------- K4: loss (grid-parallel, last block finalizes) -----------
__global__ void __launch_bounds__(256) k_loss(const float* __restrict__ pos,
                                              float* __restrict__ out, int loss_idx) {
    int i = blockIdx.x * 256 + threadIdx.x;
    float t = 0.f;
    #pragma unroll
    for (int s = 0; s < NSLOT; ++s) t += g_negp[s][i];
    float v = __logf(1.0f + __fdividef(t, pos[i]));
    v = warp_sum(v);
    __shared__ float sr[8];
    if ((threadIdx.x & 31) == 0) sr[threadIdx.x >> 5] = v;
    __syncthreads();
    if (threadIdx.x == 0) {
        float s = 0.f;
        #pragma unroll
        for (int w = 0; w < 8; ++w) s += sr[w];
        atomicAdd(&g_lsum, s);
        __threadfence();
        if (atomicAdd(&g_cnt, 1) == (N_ / 256) - 1) {
            out[loss_idx] = g_lsum * (1.0f / (float)N_);
            g_cnt = 0;
        }
    }
}

// ---------------- launch ----------------
extern "C" void kernel_launch(void* const* d_in, const int* in_sizes, int n_in,
                              void* d_out, int out_size) {
    const float* rep    = (const float*)d_in[0];
    const float* aug    = (const float*)d_in[1];
    const float* rel    = (const float*)d_in[2];
    const float* cls_w  = (const float*)d_in[3];
    const float* cls_b  = (const float*)d_in[4];
    const int*   labels = (const int*)d_in[5];
    const float* temp   = (const float*)d_in[6];
    float* out = (float*)d_out;

    static cudaStream_t s2 = nullptr;
    static cudaEvent_t evA = nullptr, evB = nullptr;
    if (!s2) {
        cudaFuncSetAttribute(k_pair_hmma, cudaFuncAttributeMaxDynamicSharedMemorySize, PAIR_SMEM);
        cudaStreamCreateWithFlags(&s2, cudaStreamNonBlocking);
        cudaEventCreateWithFlags(&evA, cudaEventDisableTiming);
        cudaEventCreateWithFlags(&evB, cudaEventDisableTiming);
    }

    // critical path: k_bag -> k_pair -> k_loss
    k_bag<<<B_, 256>>>(rep, rel, labels);

    // fork: classifier + pos run on s2, overlapping the pair GEMM
    cudaEventRecord(evA, 0);
    cudaStreamWaitEvent(s2, evA, 0);
    k_clsout<<<B_ / 8, 256, 0, s2>>>(cls_w, cls_b, out);
    k_pos<<<B_, 256, 0, s2>>>(rep, aug, temp);
    cudaEventRecord(evB, s2);

    dim3 g3(N_ / 128, B_ / 128);   // (128, 4)
    k_pair_hmma<<<g3, 256, PAIR_SMEM>>>(temp);

    // join: k_loss needs g_pos (s2) and g_negp (main)
    cudaStreamWaitEvent(0, evB, 0);
    float* g_pos_ptr = nullptr;
    cudaGetSymbolAddress((void**)&g_pos_ptr, g_pos);
    k_loss<<<N_ / 256, 256>>>(g_pos_ptr, out, out_size - 1);
}